// round 1
// baseline (speedup 1.0000x reference)
#include <cuda_runtime.h>
#include <math.h>

#define T_TOK 1024
#define HDIM  2048
#define NEXP  64
#define IDIM  768
#define TOPK  8

// ---------------- device scratch (no allocations allowed) ----------------
__device__ int   g_count[NEXP];                    // tokens routed per expert
__device__ int   g_entry[NEXP * T_TOK];            // token*8 + slot
__device__ float g_wt   [NEXP * T_TOK];            // renormalized routing weight
__device__ float g_act  [T_TOK * TOPK * IDIM];     // gathered silu(g)*u*w  (25 MB)

// ---------------- kernel 0: reset counters ----------------
__global__ void zero_counts_kernel() {
    if (threadIdx.x < NEXP) g_count[threadIdx.x] = 0;
}

// ---------------- kernel 1: router GEMM + top-8 + bucket scatter ----------------
// grid = T/64 blocks, 256 threads. Each block: 64 tokens x 64 experts logits,
// then per-token top-8 selection and bucket write.
__global__ __launch_bounds__(256)
void router_kernel(const float* __restrict__ x, const float* __restrict__ gw) {
    __shared__ float As[16][68];
    __shared__ float Bs[16][68];
    __shared__ float Ls[64][65];

    const int t0  = blockIdx.x * 64;
    const int tid = threadIdx.x;
    const int tx  = tid & 15;
    const int ty  = tid >> 4;
    const int m   = tid & 63;    // A row / B expert index for loads
    const int kg  = tid >> 6;    // k-group 0..3

    float acc[4][4];
#pragma unroll
    for (int i = 0; i < 4; i++)
#pragma unroll
        for (int j = 0; j < 4; j++) acc[i][j] = 0.f;

    for (int k0 = 0; k0 < HDIM; k0 += 16) {
        float4 av = *(const float4*)(x  + (size_t)(t0 + m) * HDIM + k0 + kg * 4);
        float4 bv = *(const float4*)(gw + (size_t)m * HDIM        + k0 + kg * 4);
        As[kg*4+0][m] = av.x; As[kg*4+1][m] = av.y; As[kg*4+2][m] = av.z; As[kg*4+3][m] = av.w;
        Bs[kg*4+0][m] = bv.x; Bs[kg*4+1][m] = bv.y; Bs[kg*4+2][m] = bv.z; Bs[kg*4+3][m] = bv.w;
        __syncthreads();
#pragma unroll
        for (int kk = 0; kk < 16; kk++) {
            float a[4], b[4];
#pragma unroll
            for (int i = 0; i < 4; i++) a[i] = As[kk][ty*4 + i];
#pragma unroll
            for (int j = 0; j < 4; j++) b[j] = Bs[kk][tx*4 + j];
#pragma unroll
            for (int i = 0; i < 4; i++)
#pragma unroll
                for (int j = 0; j < 4; j++) acc[i][j] += a[i] * b[j];
        }
        __syncthreads();
    }

#pragma unroll
    for (int i = 0; i < 4; i++)
#pragma unroll
        for (int j = 0; j < 4; j++) Ls[ty*4 + i][tx*4 + j] = acc[i][j];
    __syncthreads();

    // one thread per token: top-8 on logits (softmax Z cancels under renorm)
    if (tid < 64) {
        int   sel[TOPK];
        float sv [TOPK];
        unsigned long long mask = 0ull;
#pragma unroll
        for (int k = 0; k < TOPK; k++) {
            float best = -1e30f;
            int   be   = 0;
            for (int e = 0; e < NEXP; e++) {
                if ((mask >> e) & 1ull) continue;
                float v = Ls[tid][e];
                if (v > best) { best = v; be = e; }
            }
            mask |= (1ull << be);
            sel[k] = be;
            sv[k]  = best;
        }
        float mx = sv[0];
        float s  = 0.f;
#pragma unroll
        for (int k = 0; k < TOPK; k++) { sv[k] = expf(sv[k] - mx); s += sv[k]; }
        float inv = 1.f / s;
#pragma unroll
        for (int k = 0; k < TOPK; k++) {
            int e   = sel[k];
            int pos = atomicAdd(&g_count[e], 1);
            g_entry[e * T_TOK + pos] = (t0 + tid) * TOPK + k;
            g_wt   [e * T_TOK + pos] = sv[k] * inv;
        }
    }
}

// ---------------- kernel 2: grouped dual GEMM gate+up, fused SwiGLU ----------------
// grid = (IDIM/64, 16, NEXP), 256 threads. BM=64 tokens, BN=64, BK=16.
__global__ __launch_bounds__(256)
void gateup_kernel(const float* __restrict__ x,
                   const float* __restrict__ wg,
                   const float* __restrict__ wu) {
    const int e   = blockIdx.z;
    const int cnt = g_count[e];
    const int m0  = blockIdx.y * 64;
    if (m0 >= cnt) return;
    const int n0  = blockIdx.x * 64;

    __shared__ float As[16][68];
    __shared__ float Bg[16][68];
    __shared__ float Bu[16][68];
    __shared__ int   sEnt[64];
    __shared__ float sW[64];

    const int tid = threadIdx.x;
    if (tid < 64) {
        int mi = m0 + tid;
        if (mi < cnt) { sEnt[tid] = g_entry[e * T_TOK + mi]; sW[tid] = g_wt[e * T_TOK + mi]; }
        else          { sEnt[tid] = -1;                      sW[tid] = 0.f; }
    }
    __syncthreads();

    const int tx = tid & 15;
    const int ty = tid >> 4;
    const int m  = tid & 63;
    const int kg = tid >> 6;
    const int nb = (tid & 15) * 4;
    const int kb = tid >> 4;

    const int ent = sEnt[m];
    const float* xrow = (ent >= 0) ? (x + (size_t)(ent >> 3) * HDIM) : x;
    const bool   avalid = (ent >= 0);

    const float* wge = wg + (size_t)e * HDIM * IDIM;
    const float* wue = wu + (size_t)e * HDIM * IDIM;

    float ag[4][4], au[4][4];
#pragma unroll
    for (int i = 0; i < 4; i++)
#pragma unroll
        for (int j = 0; j < 4; j++) { ag[i][j] = 0.f; au[i][j] = 0.f; }

    for (int k0 = 0; k0 < HDIM; k0 += 16) {
        float4 av = avalid ? *(const float4*)(xrow + k0 + kg * 4)
                           : make_float4(0.f, 0.f, 0.f, 0.f);
        As[kg*4+0][m] = av.x; As[kg*4+1][m] = av.y; As[kg*4+2][m] = av.z; As[kg*4+3][m] = av.w;

        float4 bgv = *(const float4*)(wge + (size_t)(k0 + kb) * IDIM + n0 + nb);
        float4 buv = *(const float4*)(wue + (size_t)(k0 + kb) * IDIM + n0 + nb);
        *(float4*)&Bg[kb][nb] = bgv;
        *(float4*)&Bu[kb][nb] = buv;
        __syncthreads();
#pragma unroll
        for (int kk = 0; kk < 16; kk++) {
            float a[4], bg[4], bu[4];
#pragma unroll
            for (int i = 0; i < 4; i++) a[i]  = As[kk][ty*4 + i];
#pragma unroll
            for (int j = 0; j < 4; j++) { bg[j] = Bg[kk][tx*4 + j]; bu[j] = Bu[kk][tx*4 + j]; }
#pragma unroll
            for (int i = 0; i < 4; i++)
#pragma unroll
                for (int j = 0; j < 4; j++) {
                    ag[i][j] += a[i] * bg[j];
                    au[i][j] += a[i] * bu[j];
                }
        }
        __syncthreads();
    }

#pragma unroll
    for (int i = 0; i < 4; i++) {
        int mi = ty * 4 + i;
        int en = sEnt[mi];
        if (en < 0) continue;
        float w = sW[mi];
        float* arow = g_act + (size_t)en * IDIM + n0;
#pragma unroll
        for (int j = 0; j < 4; j++) {
            float g = ag[i][j];
            float u = au[i][j];
            float sg = g / (1.f + expf(-g));   // silu
            arow[tx*4 + j] = sg * u * w;
        }
    }
}

// ---------------- kernel 3: grouped down GEMM, atomic scatter-add ----------------
// grid = (HDIM/64, 16, NEXP), 256 threads. BM=64, BN=64, BK=16, K=IDIM.
__global__ __launch_bounds__(256)
void down_kernel(const float* __restrict__ wd, float* __restrict__ out) {
    const int e   = blockIdx.z;
    const int cnt = g_count[e];
    const int m0  = blockIdx.y * 64;
    if (m0 >= cnt) return;
    const int h0  = blockIdx.x * 64;

    __shared__ float As[16][68];
    __shared__ float Bs[16][68];
    __shared__ int   sEnt[64];

    const int tid = threadIdx.x;
    if (tid < 64) {
        int mi = m0 + tid;
        sEnt[tid] = (mi < cnt) ? g_entry[e * T_TOK + mi] : -1;
    }
    __syncthreads();

    const int tx = tid & 15;
    const int ty = tid >> 4;
    const int m  = tid & 63;
    const int kg = tid >> 6;
    const int nb = (tid & 15) * 4;
    const int kb = tid >> 4;

    const int ent = sEnt[m];
    const float* arow = (ent >= 0) ? (g_act + (size_t)ent * IDIM) : g_act;
    const bool   avalid = (ent >= 0);

    const float* wde = wd + (size_t)e * IDIM * HDIM;

    float acc[4][4];
#pragma unroll
    for (int i = 0; i < 4; i++)
#pragma unroll
        for (int j = 0; j < 4; j++) acc[i][j] = 0.f;

    for (int k0 = 0; k0 < IDIM; k0 += 16) {
        float4 av = avalid ? *(const float4*)(arow + k0 + kg * 4)
                           : make_float4(0.f, 0.f, 0.f, 0.f);
        As[kg*4+0][m] = av.x; As[kg*4+1][m] = av.y; As[kg*4+2][m] = av.z; As[kg*4+3][m] = av.w;

        float4 bv = *(const float4*)(wde + (size_t)(k0 + kb) * HDIM + h0 + nb);
        *(float4*)&Bs[kb][nb] = bv;
        __syncthreads();
#pragma unroll
        for (int kk = 0; kk < 16; kk++) {
            float a[4], b[4];
#pragma unroll
            for (int i = 0; i < 4; i++) a[i] = As[kk][ty*4 + i];
#pragma unroll
            for (int j = 0; j < 4; j++) b[j] = Bs[kk][tx*4 + j];
#pragma unroll
            for (int i = 0; i < 4; i++)
#pragma unroll
                for (int j = 0; j < 4; j++) acc[i][j] += a[i] * b[j];
        }
        __syncthreads();
    }

#pragma unroll
    for (int i = 0; i < 4; i++) {
        int mi = ty * 4 + i;
        int en = sEnt[mi];
        if (en < 0) continue;
        int tok = en >> 3;
        float* orow = out + (size_t)tok * HDIM + h0;
#pragma unroll
        for (int j = 0; j < 4; j++)
            atomicAdd(&orow[tx*4 + j], acc[i][j]);
    }
}

// ---------------- launch ----------------
extern "C" void kernel_launch(void* const* d_in, const int* in_sizes, int n_in,
                              void* d_out, int out_size) {
    const float* x  = (const float*)d_in[0];   // [T, H]
    const float* gw = (const float*)d_in[1];   // [E, H]
    const float* wg = (const float*)d_in[2];   // [E, H, I]
    const float* wu = (const float*)d_in[3];   // [E, H, I]
    const float* wd = (const float*)d_in[4];   // [E, I, H]
    float* out = (float*)d_out;                // [T, H]

    cudaMemsetAsync(out, 0, (size_t)T_TOK * HDIM * sizeof(float));

    zero_counts_kernel<<<1, 64>>>();
    router_kernel<<<T_TOK / 64, 256>>>(x, gw);

    dim3 gu_grid(IDIM / 64, T_TOK / 64, NEXP);
    gateup_kernel<<<gu_grid, 256>>>(x, wg, wu);

    dim3 dn_grid(HDIM / 64, T_TOK / 64, NEXP);
    down_kernel<<<dn_grid, 256>>>(wd, out);
}

// round 3
// speedup vs baseline: 1.8265x; 1.8265x over previous
#include <cuda_runtime.h>
#include <cuda_fp16.h>
#include <math.h>
#include <stdint.h>

#define T_TOK 1024
#define HDIM  2048
#define NEXP  64
#define IDIM  768
#define TOPK  8

// ---------------- device scratch ----------------
__device__ int   g_count[NEXP];
__device__ int   g_entry[NEXP * T_TOK];            // token*8 + slot
__device__ float g_wt   [NEXP * T_TOK];
__device__ float g_act  [T_TOK * TOPK * IDIM];     // fp32 silu(g)*u*w, gathered

// ---------------- helpers ----------------
__device__ __forceinline__ uint32_t smem_u32(const void* p) {
    uint32_t a;
    asm("{ .reg .u64 t; cvta.to.shared.u64 t, %1; cvt.u32.u64 %0, t; }" : "=r"(a) : "l"(p));
    return a;
}
__device__ __forceinline__ void sts128(uint32_t a, uint32_t x, uint32_t y, uint32_t z, uint32_t w) {
    asm volatile("st.shared.v4.b32 [%0], {%1,%2,%3,%4};" :: "r"(a), "r"(x), "r"(y), "r"(z), "r"(w));
}
__device__ __forceinline__ void ldsm4(uint32_t& r0, uint32_t& r1, uint32_t& r2, uint32_t& r3, uint32_t a) {
    asm volatile("ldmatrix.sync.aligned.m8n8.x4.shared.b16 {%0,%1,%2,%3}, [%4];"
                 : "=r"(r0), "=r"(r1), "=r"(r2), "=r"(r3) : "r"(a));
}
__device__ __forceinline__ void ldsm4t(uint32_t& r0, uint32_t& r1, uint32_t& r2, uint32_t& r3, uint32_t a) {
    asm volatile("ldmatrix.sync.aligned.m8n8.x4.trans.shared.b16 {%0,%1,%2,%3}, [%4];"
                 : "=r"(r0), "=r"(r1), "=r"(r2), "=r"(r3) : "r"(a));
}
__device__ __forceinline__ void mma_h(float& c0, float& c1, float& c2, float& c3,
                                      uint32_t a0, uint32_t a1, uint32_t a2, uint32_t a3,
                                      uint32_t b0, uint32_t b1) {
    asm volatile("mma.sync.aligned.m16n8k16.row.col.f32.f16.f16.f32 "
                 "{%0,%1,%2,%3},{%4,%5,%6,%7},{%8,%9},{%0,%1,%2,%3};"
                 : "+f"(c0), "+f"(c1), "+f"(c2), "+f"(c3)
                 : "r"(a0), "r"(a1), "r"(a2), "r"(a3), "r"(b0), "r"(b1));
}
__device__ __forceinline__ uint32_t packh(__half lo, __half hi) {
    return (uint32_t)__half_as_ushort(lo) | ((uint32_t)__half_as_ushort(hi) << 16);
}
// split fp32x4 -> fp16 hi (2 regs) + fp16 lo (2 regs)
__device__ __forceinline__ void cvt4h(float4 f, uint32_t& h0, uint32_t& h1,
                                      uint32_t& l0, uint32_t& l1) {
    __half ax = __float2half_rn(f.x), ay = __float2half_rn(f.y);
    __half az = __float2half_rn(f.z), aw = __float2half_rn(f.w);
    __half bx = __float2half_rn(f.x - __half2float(ax));
    __half by = __float2half_rn(f.y - __half2float(ay));
    __half bz = __float2half_rn(f.z - __half2float(az));
    __half bw = __float2half_rn(f.w - __half2float(aw));
    h0 = packh(ax, ay); h1 = packh(az, aw);
    l0 = packh(bx, by); l1 = packh(bz, bw);
}

// smem geometry (fp16 elems): A tile 128x32, row stride 40 (80B, conflict-free)
//                             B tile  32x64, row stride 72 (144B, conflict-free)
#define A_BYTES 10240   // 128*40*2
#define B_BYTES 4608    // 32*72*2

// ---------------- kernel 0: reset counters ----------------
__global__ void zero_counts_kernel() {
    if (threadIdx.x < NEXP) g_count[threadIdx.x] = 0;
}

// ---------------- kernel 1: router GEMM + top-8 + bucket scatter ----------------
__global__ __launch_bounds__(256)
void router_kernel(const float* __restrict__ x, const float* __restrict__ gw) {
    __shared__ float As[16][68];
    __shared__ float Bs[16][68];
    __shared__ float Ls[64][65];

    const int t0  = blockIdx.x * 64;
    const int tid = threadIdx.x;
    const int tx  = tid & 15;
    const int ty  = tid >> 4;
    const int m   = tid & 63;
    const int kg  = tid >> 6;

    float acc[4][4];
#pragma unroll
    for (int i = 0; i < 4; i++)
#pragma unroll
        for (int j = 0; j < 4; j++) acc[i][j] = 0.f;

    for (int k0 = 0; k0 < HDIM; k0 += 16) {
        float4 av = *(const float4*)(x  + (size_t)(t0 + m) * HDIM + k0 + kg * 4);
        float4 bv = *(const float4*)(gw + (size_t)m * HDIM        + k0 + kg * 4);
        As[kg*4+0][m] = av.x; As[kg*4+1][m] = av.y; As[kg*4+2][m] = av.z; As[kg*4+3][m] = av.w;
        Bs[kg*4+0][m] = bv.x; Bs[kg*4+1][m] = bv.y; Bs[kg*4+2][m] = bv.z; Bs[kg*4+3][m] = bv.w;
        __syncthreads();
#pragma unroll
        for (int kk = 0; kk < 16; kk++) {
            float a[4], b[4];
#pragma unroll
            for (int i = 0; i < 4; i++) a[i] = As[kk][ty*4 + i];
#pragma unroll
            for (int j = 0; j < 4; j++) b[j] = Bs[kk][tx*4 + j];
#pragma unroll
            for (int i = 0; i < 4; i++)
#pragma unroll
                for (int j = 0; j < 4; j++) acc[i][j] += a[i] * b[j];
        }
        __syncthreads();
    }

#pragma unroll
    for (int i = 0; i < 4; i++)
#pragma unroll
        for (int j = 0; j < 4; j++) Ls[ty*4 + i][tx*4 + j] = acc[i][j];
    __syncthreads();

    if (tid < 64) {
        int   sel[TOPK];
        float sv [TOPK];
        unsigned long long mask = 0ull;
#pragma unroll
        for (int k = 0; k < TOPK; k++) {
            float best = -1e30f;
            int   be   = 0;
            for (int e = 0; e < NEXP; e++) {
                if ((mask >> e) & 1ull) continue;
                float v = Ls[tid][e];
                if (v > best) { best = v; be = e; }
            }
            mask |= (1ull << be);
            sel[k] = be;
            sv[k]  = best;
        }
        float mx = sv[0];
        float s  = 0.f;
#pragma unroll
        for (int k = 0; k < TOPK; k++) { sv[k] = expf(sv[k] - mx); s += sv[k]; }
        float inv = 1.f / s;
#pragma unroll
        for (int k = 0; k < TOPK; k++) {
            int e   = sel[k];
            int pos = atomicAdd(&g_count[e], 1);
            g_entry[e * T_TOK + pos] = (t0 + tid) * TOPK + k;
            g_wt   [e * T_TOK + pos] = sv[k] * inv;
        }
    }
}

// ---------------- kernel 2: gate+up HMMA GEMM, fused SwiGLU ----------------
// BM=128 gathered tokens, BN=64 (both gate & up), BK=32, fp16 hi/lo split.
#define GU_BUF  (2 * A_BYTES + 4 * B_BYTES)          // 38912
#define GU_SMEM (1024 + 2 * GU_BUF)                  // 78848

__global__ __launch_bounds__(256, 1)
void gateup_mma(const float* __restrict__ x,
                const float* __restrict__ wg,
                const float* __restrict__ wu) {
    extern __shared__ char smem[];
    const int e   = blockIdx.z;
    const int cnt = g_count[e];
    const int m0  = blockIdx.y * 128;
    if (m0 >= cnt) return;
    const int n0  = blockIdx.x * 64;
    const int tid  = threadIdx.x;
    const int wid  = tid >> 5;
    const int lane = tid & 31;

    const uint32_t sb = smem_u32(smem);
    int*   sEnt = (int*)smem;
    float* sW   = (float*)(smem + 512);

    if (tid < 128) {
        int mi = m0 + tid;
        if (mi < cnt) { sEnt[tid] = g_entry[e * T_TOK + mi]; sW[tid] = g_wt[e * T_TOK + mi]; }
        else          { sEnt[tid] = -1;                      sW[tid] = 0.f; }
    }
    __syncthreads();

    // loader mappings
    const int arow = tid >> 1, akh = (tid & 1) * 16;
    const int aent = sEnt[arow];
    const float* ax = x + (size_t)(aent >= 0 ? (aent >> 3) : 0) * HDIM + akh;
    const int brow = tid >> 3, bcol = (tid & 7) * 8;
    const float* pg = wg + (size_t)e * HDIM * IDIM + n0 + bcol;
    const float* pu = wu + (size_t)e * HDIM * IDIM + n0 + bcol;

    float4 fA[4], fG[2], fU[2];
    auto loadRegs = [&](int k0) {
        if (aent >= 0) {
            fA[0] = *(const float4*)(ax + k0);
            fA[1] = *(const float4*)(ax + k0 + 4);
            fA[2] = *(const float4*)(ax + k0 + 8);
            fA[3] = *(const float4*)(ax + k0 + 12);
        } else {
            fA[0] = make_float4(0.f, 0.f, 0.f, 0.f);
            fA[1] = fA[2] = fA[3] = fA[0];
        }
        const float* gp = pg + (size_t)(k0 + brow) * IDIM;
        const float* up = pu + (size_t)(k0 + brow) * IDIM;
        fG[0] = *(const float4*)gp; fG[1] = *(const float4*)(gp + 4);
        fU[0] = *(const float4*)up; fU[1] = *(const float4*)(up + 4);
    };

    auto stsRegs = [&](int b) {
        const uint32_t base = sb + 1024 + b * GU_BUF;
        const uint32_t Ah = base, Al = base + A_BYTES;
        const uint32_t Bgh = base + 2 * A_BYTES, Bgl = Bgh + B_BYTES;
        const uint32_t Buh = Bgl + B_BYTES,      Bul = Buh + B_BYTES;
        uint32_t h0, h1, l0, l1, h2, h3, l2, l3;
        const uint32_t offA = arow * 80 + akh * 2;
        cvt4h(fA[0], h0, h1, l0, l1); cvt4h(fA[1], h2, h3, l2, l3);
        sts128(Ah + offA, h0, h1, h2, h3); sts128(Al + offA, l0, l1, l2, l3);
        cvt4h(fA[2], h0, h1, l0, l1); cvt4h(fA[3], h2, h3, l2, l3);
        sts128(Ah + offA + 16, h0, h1, h2, h3); sts128(Al + offA + 16, l0, l1, l2, l3);
        const uint32_t offB = brow * 144 + bcol * 2;
        cvt4h(fG[0], h0, h1, l0, l1); cvt4h(fG[1], h2, h3, l2, l3);
        sts128(Bgh + offB, h0, h1, h2, h3); sts128(Bgl + offB, l0, l1, l2, l3);
        cvt4h(fU[0], h0, h1, l0, l1); cvt4h(fU[1], h2, h3, l2, l3);
        sts128(Buh + offB, h0, h1, h2, h3); sts128(Bul + offB, l0, l1, l2, l3);
    };

    const int wm = wid >> 1, wn = wid & 1;
    float accg[2][4][4], accu[2][4][4];
#pragma unroll
    for (int i = 0; i < 2; i++)
#pragma unroll
        for (int j = 0; j < 4; j++)
#pragma unroll
            for (int q = 0; q < 4; q++) { accg[i][j][q] = 0.f; accu[i][j][q] = 0.f; }

    auto compute = [&](int b) {
        const uint32_t base = sb + 1024 + b * GU_BUF;
        const uint32_t Ah = base, Al = base + A_BYTES;
        const uint32_t Bgh = base + 2 * A_BYTES, Bgl = Bgh + B_BYTES;
        const uint32_t Buh = Bgl + B_BYTES,      Bul = Buh + B_BYTES;
#pragma unroll
        for (int kk = 0; kk < 2; kk++) {
            uint32_t ah[2][4], al[2][4];
            const uint32_t acol = (kk * 16 + (lane >> 4) * 8) * 2;
#pragma unroll
            for (int i = 0; i < 2; i++) {
                uint32_t ra = (wm * 32 + i * 16 + (lane & 15)) * 80 + acol;
                ldsm4(ah[i][0], ah[i][1], ah[i][2], ah[i][3], Ah + ra);
                ldsm4(al[i][0], al[i][1], al[i][2], al[i][3], Al + ra);
            }
            const uint32_t brow_ = kk * 16 + ((lane >> 3) & 1) * 8 + (lane & 7);
#pragma unroll
            for (int hf = 0; hf < 2; hf++) {
                const uint32_t rb = brow_ * 144 + (wn * 32 + hf * 16 + (lane >> 4) * 8) * 2;
                uint32_t g0, g1, g2, g3, gl0, gl1, gl2, gl3;
                ldsm4t(g0, g1, g2, g3, Bgh + rb);
                ldsm4t(gl0, gl1, gl2, gl3, Bgl + rb);
#pragma unroll
                for (int i = 0; i < 2; i++) {
                    float* c0 = accg[i][hf * 2 + 0];
                    float* c1 = accg[i][hf * 2 + 1];
                    mma_h(c0[0], c0[1], c0[2], c0[3], ah[i][0], ah[i][1], ah[i][2], ah[i][3], g0, g1);
                    mma_h(c0[0], c0[1], c0[2], c0[3], ah[i][0], ah[i][1], ah[i][2], ah[i][3], gl0, gl1);
                    mma_h(c0[0], c0[1], c0[2], c0[3], al[i][0], al[i][1], al[i][2], al[i][3], g0, g1);
                    mma_h(c1[0], c1[1], c1[2], c1[3], ah[i][0], ah[i][1], ah[i][2], ah[i][3], g2, g3);
                    mma_h(c1[0], c1[1], c1[2], c1[3], ah[i][0], ah[i][1], ah[i][2], ah[i][3], gl2, gl3);
                    mma_h(c1[0], c1[1], c1[2], c1[3], al[i][0], al[i][1], al[i][2], al[i][3], g2, g3);
                }
                uint32_t u0, u1, u2, u3, ul0, ul1, ul2, ul3;
                ldsm4t(u0, u1, u2, u3, Buh + rb);
                ldsm4t(ul0, ul1, ul2, ul3, Bul + rb);
#pragma unroll
                for (int i = 0; i < 2; i++) {
                    float* c0 = accu[i][hf * 2 + 0];
                    float* c1 = accu[i][hf * 2 + 1];
                    mma_h(c0[0], c0[1], c0[2], c0[3], ah[i][0], ah[i][1], ah[i][2], ah[i][3], u0, u1);
                    mma_h(c0[0], c0[1], c0[2], c0[3], ah[i][0], ah[i][1], ah[i][2], ah[i][3], ul0, ul1);
                    mma_h(c0[0], c0[1], c0[2], c0[3], al[i][0], al[i][1], al[i][2], al[i][3], u0, u1);
                    mma_h(c1[0], c1[1], c1[2], c1[3], ah[i][0], ah[i][1], ah[i][2], ah[i][3], u2, u3);
                    mma_h(c1[0], c1[1], c1[2], c1[3], ah[i][0], ah[i][1], ah[i][2], ah[i][3], ul2, ul3);
                    mma_h(c1[0], c1[1], c1[2], c1[3], al[i][0], al[i][1], al[i][2], al[i][3], u2, u3);
                }
            }
        }
    };

    loadRegs(0);
    stsRegs(0);
    __syncthreads();

    const int C = HDIM / 32;
    for (int c = 0; c < C; c++) {
        if (c + 1 < C) loadRegs((c + 1) * 32);
        compute(c & 1);
        if (c + 1 < C) { stsRegs((c + 1) & 1); __syncthreads(); }
    }

    // epilogue: silu(g)*u*w -> g_act
#pragma unroll
    for (int i = 0; i < 2; i++)
#pragma unroll
        for (int nt = 0; nt < 4; nt++) {
            const int r    = wm * 32 + i * 16 + (lane >> 2);
            const int cof  = n0 + wn * 32 + nt * 8 + (lane & 3) * 2;
#pragma unroll
            for (int half = 0; half < 2; half++) {
                const int rr  = r + half * 8;
                const int ent = sEnt[rr];
                if (ent >= 0) {
                    const float w = sW[rr];
                    float g0 = accg[i][nt][half * 2 + 0], g1 = accg[i][nt][half * 2 + 1];
                    float u0 = accu[i][nt][half * 2 + 0], u1 = accu[i][nt][half * 2 + 1];
                    float2 st;
                    st.x = g0 / (1.f + expf(-g0)) * u0 * w;
                    st.y = g1 / (1.f + expf(-g1)) * u1 * w;
                    *(float2*)(g_act + (size_t)ent * IDIM + cof) = st;
                }
            }
        }
}

// ---------------- kernel 3: down HMMA GEMM, atomic scatter ----------------
#define DN_BUF  (2 * A_BYTES + 2 * B_BYTES)          // 29696
#define DN_SMEM (1024 + 2 * DN_BUF)                  // 60416

__global__ __launch_bounds__(256, 1)
void down_mma(const float* __restrict__ wd, float* __restrict__ out) {
    extern __shared__ char smem[];
    const int e   = blockIdx.z;
    const int cnt = g_count[e];
    const int m0  = blockIdx.y * 128;
    if (m0 >= cnt) return;
    const int n0  = blockIdx.x * 64;
    const int tid  = threadIdx.x;
    const int wid  = tid >> 5;
    const int lane = tid & 31;

    const uint32_t sb = smem_u32(smem);
    int* sEnt = (int*)smem;

    if (tid < 128) {
        int mi = m0 + tid;
        sEnt[tid] = (mi < cnt) ? g_entry[e * T_TOK + mi] : -1;
    }
    __syncthreads();

    const int arow = tid >> 1, akh = (tid & 1) * 16;
    const int aent = sEnt[arow];
    const float* ax = g_act + (size_t)(aent >= 0 ? aent : 0) * IDIM + akh;
    const int brow = tid >> 3, bcol = (tid & 7) * 8;
    const float* pb = wd + (size_t)e * IDIM * HDIM + n0 + bcol;

    float4 fA[4], fB[2];
    auto loadRegs = [&](int k0) {
        if (aent >= 0) {
            fA[0] = *(const float4*)(ax + k0);
            fA[1] = *(const float4*)(ax + k0 + 4);
            fA[2] = *(const float4*)(ax + k0 + 8);
            fA[3] = *(const float4*)(ax + k0 + 12);
        } else {
            fA[0] = make_float4(0.f, 0.f, 0.f, 0.f);
            fA[1] = fA[2] = fA[3] = fA[0];
        }
        const float* bp = pb + (size_t)(k0 + brow) * HDIM;
        fB[0] = *(const float4*)bp; fB[1] = *(const float4*)(bp + 4);
    };

    auto stsRegs = [&](int b) {
        const uint32_t base = sb + 1024 + b * DN_BUF;
        const uint32_t Ah = base, Al = base + A_BYTES;
        const uint32_t Bh = base + 2 * A_BYTES, Bl = Bh + B_BYTES;
        uint32_t h0, h1, l0, l1, h2, h3, l2, l3;
        const uint32_t offA = arow * 80 + akh * 2;
        cvt4h(fA[0], h0, h1, l0, l1); cvt4h(fA[1], h2, h3, l2, l3);
        sts128(Ah + offA, h0, h1, h2, h3); sts128(Al + offA, l0, l1, l2, l3);
        cvt4h(fA[2], h0, h1, l0, l1); cvt4h(fA[3], h2, h3, l2, l3);
        sts128(Ah + offA + 16, h0, h1, h2, h3); sts128(Al + offA + 16, l0, l1, l2, l3);
        const uint32_t offB = brow * 144 + bcol * 2;
        cvt4h(fB[0], h0, h1, l0, l1); cvt4h(fB[1], h2, h3, l2, l3);
        sts128(Bh + offB, h0, h1, h2, h3); sts128(Bl + offB, l0, l1, l2, l3);
    };

    const int wm = wid >> 1, wn = wid & 1;
    float acc[2][4][4];
#pragma unroll
    for (int i = 0; i < 2; i++)
#pragma unroll
        for (int j = 0; j < 4; j++)
#pragma unroll
            for (int q = 0; q < 4; q++) acc[i][j][q] = 0.f;

    auto compute = [&](int b) {
        const uint32_t base = sb + 1024 + b * DN_BUF;
        const uint32_t Ah = base, Al = base + A_BYTES;
        const uint32_t Bh = base + 2 * A_BYTES, Bl = Bh + B_BYTES;
#pragma unroll
        for (int kk = 0; kk < 2; kk++) {
            uint32_t ah[2][4], al[2][4];
            const uint32_t acol = (kk * 16 + (lane >> 4) * 8) * 2;
#pragma unroll
            for (int i = 0; i < 2; i++) {
                uint32_t ra = (wm * 32 + i * 16 + (lane & 15)) * 80 + acol;
                ldsm4(ah[i][0], ah[i][1], ah[i][2], ah[i][3], Ah + ra);
                ldsm4(al[i][0], al[i][1], al[i][2], al[i][3], Al + ra);
            }
            const uint32_t brow_ = kk * 16 + ((lane >> 3) & 1) * 8 + (lane & 7);
#pragma unroll
            for (int hf = 0; hf < 2; hf++) {
                const uint32_t rb = brow_ * 144 + (wn * 32 + hf * 16 + (lane >> 4) * 8) * 2;
                uint32_t b0, b1, b2, b3, bl0, bl1, bl2, bl3;
                ldsm4t(b0, b1, b2, b3, Bh + rb);
                ldsm4t(bl0, bl1, bl2, bl3, Bl + rb);
#pragma unroll
                for (int i = 0; i < 2; i++) {
                    float* c0 = acc[i][hf * 2 + 0];
                    float* c1 = acc[i][hf * 2 + 1];
                    mma_h(c0[0], c0[1], c0[2], c0[3], ah[i][0], ah[i][1], ah[i][2], ah[i][3], b0, b1);
                    mma_h(c0[0], c0[1], c0[2], c0[3], ah[i][0], ah[i][1], ah[i][2], ah[i][3], bl0, bl1);
                    mma_h(c0[0], c0[1], c0[2], c0[3], al[i][0], al[i][1], al[i][2], al[i][3], b0, b1);
                    mma_h(c1[0], c1[1], c1[2], c1[3], ah[i][0], ah[i][1], ah[i][2], ah[i][3], b2, b3);
                    mma_h(c1[0], c1[1], c1[2], c1[3], ah[i][0], ah[i][1], ah[i][2], ah[i][3], bl2, bl3);
                    mma_h(c1[0], c1[1], c1[2], c1[3], al[i][0], al[i][1], al[i][2], al[i][3], b2, b3);
                }
            }
        }
    };

    loadRegs(0);
    stsRegs(0);
    __syncthreads();

    const int C = IDIM / 32;
    for (int c = 0; c < C; c++) {
        if (c + 1 < C) loadRegs((c + 1) * 32);
        compute(c & 1);
        if (c + 1 < C) { stsRegs((c + 1) & 1); __syncthreads(); }
    }

#pragma unroll
    for (int i = 0; i < 2; i++)
#pragma unroll
        for (int nt = 0; nt < 4; nt++) {
            const int r   = wm * 32 + i * 16 + (lane >> 2);
            const int cof = n0 + wn * 32 + nt * 8 + (lane & 3) * 2;
#pragma unroll
            for (int half = 0; half < 2; half++) {
                const int rr  = r + half * 8;
                const int ent = sEnt[rr];
                if (ent >= 0) {
                    float* dst = out + (size_t)(ent >> 3) * HDIM + cof;
                    atomicAdd(dst,     acc[i][nt][half * 2 + 0]);
                    atomicAdd(dst + 1, acc[i][nt][half * 2 + 1]);
                }
            }
        }
}

// ---------------- launch ----------------
extern "C" void kernel_launch(void* const* d_in, const int* in_sizes, int n_in,
                              void* d_out, int out_size) {
    const float* x  = (const float*)d_in[0];
    const float* gw = (const float*)d_in[1];
    const float* wg = (const float*)d_in[2];
    const float* wu = (const float*)d_in[3];
    const float* wd = (const float*)d_in[4];
    float* out = (float*)d_out;

    static int smem_set = 0;
    if (!smem_set) {
        cudaFuncSetAttribute(gateup_mma, cudaFuncAttributeMaxDynamicSharedMemorySize, GU_SMEM);
        cudaFuncSetAttribute(down_mma,   cudaFuncAttributeMaxDynamicSharedMemorySize, DN_SMEM);
        smem_set = 1;
    }

    cudaMemsetAsync(out, 0, (size_t)T_TOK * HDIM * sizeof(float));
    zero_counts_kernel<<<1, 64>>>();
    router_kernel<<<T_TOK / 64, 256>>>(x, gw);

    dim3 gu_grid(IDIM / 64, T_TOK / 128, NEXP);
    gateup_mma<<<gu_grid, 256, GU_SMEM>>>(x, wg, wu);

    dim3 dn_grid(HDIM / 64, T_TOK / 128, NEXP);
    down_mma<<<dn_grid, 256, DN_SMEM>>>(wd, out);
}

// round 4
// speedup vs baseline: 1.9318x; 1.0576x over previous
#include <cuda_runtime.h>
#include <cuda_fp16.h>
#include <math.h>
#include <stdint.h>

#define T_TOK 1024
#define HDIM  2048
#define NEXP  64
#define IDIM  768
#define TOPK  8

// ---------------- device scratch ----------------
__device__ int    g_count[NEXP];
__device__ int    g_entry[NEXP * T_TOK];           // token*8 + slot
__device__ float  g_wt   [NEXP * T_TOK];
__device__ __half g_act_h[T_TOK * TOPK * IDIM];    // fp16 hi plane of silu(g)*u*w
__device__ __half g_act_l[T_TOK * TOPK * IDIM];    // fp16 lo plane

// ---------------- helpers ----------------
__device__ __forceinline__ uint32_t smem_u32(const void* p) {
    uint32_t a;
    asm("{ .reg .u64 t; cvta.to.shared.u64 t, %1; cvt.u32.u64 %0, t; }" : "=r"(a) : "l"(p));
    return a;
}
__device__ __forceinline__ void sts128(uint32_t a, uint32_t x, uint32_t y, uint32_t z, uint32_t w) {
    asm volatile("st.shared.v4.b32 [%0], {%1,%2,%3,%4};" :: "r"(a), "r"(x), "r"(y), "r"(z), "r"(w));
}
__device__ __forceinline__ void ldsm4(uint32_t& r0, uint32_t& r1, uint32_t& r2, uint32_t& r3, uint32_t a) {
    asm volatile("ldmatrix.sync.aligned.m8n8.x4.shared.b16 {%0,%1,%2,%3}, [%4];"
                 : "=r"(r0), "=r"(r1), "=r"(r2), "=r"(r3) : "r"(a));
}
__device__ __forceinline__ void ldsm4t(uint32_t& r0, uint32_t& r1, uint32_t& r2, uint32_t& r3, uint32_t a) {
    asm volatile("ldmatrix.sync.aligned.m8n8.x4.trans.shared.b16 {%0,%1,%2,%3}, [%4];"
                 : "=r"(r0), "=r"(r1), "=r"(r2), "=r"(r3) : "r"(a));
}
__device__ __forceinline__ void mma_h(float& c0, float& c1, float& c2, float& c3,
                                      uint32_t a0, uint32_t a1, uint32_t a2, uint32_t a3,
                                      uint32_t b0, uint32_t b1) {
    asm volatile("mma.sync.aligned.m16n8k16.row.col.f32.f16.f16.f32 "
                 "{%0,%1,%2,%3},{%4,%5,%6,%7},{%8,%9},{%0,%1,%2,%3};"
                 : "+f"(c0), "+f"(c1), "+f"(c2), "+f"(c3)
                 : "r"(a0), "r"(a1), "r"(a2), "r"(a3), "r"(b0), "r"(b1));
}
__device__ __forceinline__ uint32_t packh(__half lo, __half hi) {
    return (uint32_t)__half_as_ushort(lo) | ((uint32_t)__half_as_ushort(hi) << 16);
}
// split fp32x4 -> fp16 hi (2 regs) + fp16 lo (2 regs)
__device__ __forceinline__ void cvt4h(float4 f, uint32_t& h0, uint32_t& h1,
                                      uint32_t& l0, uint32_t& l1) {
    __half ax = __float2half_rn(f.x), ay = __float2half_rn(f.y);
    __half az = __float2half_rn(f.z), aw = __float2half_rn(f.w);
    __half bx = __float2half_rn(f.x - __half2float(ax));
    __half by = __float2half_rn(f.y - __half2float(ay));
    __half bz = __float2half_rn(f.z - __half2float(az));
    __half bw = __float2half_rn(f.w - __half2float(aw));
    h0 = packh(ax, ay); h1 = packh(az, aw);
    l0 = packh(bx, by); l1 = packh(bz, bw);
}

// smem geometry (fp16 elems): A tile 128x32, row stride 40 (80B, conflict-free)
//                             B tile  32x64, row stride 72 (144B, conflict-free)
#define A_BYTES 10240   // 128*40*2
#define B_BYTES 4608    // 32*72*2

// ---------------- kernel 0: reset counters ----------------
__global__ void zero_counts_kernel() {
    if (threadIdx.x < NEXP) g_count[threadIdx.x] = 0;
}

// ---------------- kernel 1: router GEMM + top-8 + bucket scatter ----------------
__global__ __launch_bounds__(256)
void router_kernel(const float* __restrict__ x, const float* __restrict__ gw) {
    __shared__ float As[16][68];
    __shared__ float Bs[16][68];
    __shared__ float Ls[64][65];

    const int t0  = blockIdx.x * 64;
    const int tid = threadIdx.x;
    const int tx  = tid & 15;
    const int ty  = tid >> 4;
    const int m   = tid & 63;
    const int kg  = tid >> 6;

    float acc[4][4];
#pragma unroll
    for (int i = 0; i < 4; i++)
#pragma unroll
        for (int j = 0; j < 4; j++) acc[i][j] = 0.f;

    for (int k0 = 0; k0 < HDIM; k0 += 16) {
        float4 av = *(const float4*)(x  + (size_t)(t0 + m) * HDIM + k0 + kg * 4);
        float4 bv = *(const float4*)(gw + (size_t)m * HDIM        + k0 + kg * 4);
        As[kg*4+0][m] = av.x; As[kg*4+1][m] = av.y; As[kg*4+2][m] = av.z; As[kg*4+3][m] = av.w;
        Bs[kg*4+0][m] = bv.x; Bs[kg*4+1][m] = bv.y; Bs[kg*4+2][m] = bv.z; Bs[kg*4+3][m] = bv.w;
        __syncthreads();
#pragma unroll
        for (int kk = 0; kk < 16; kk++) {
            float a[4], b[4];
#pragma unroll
            for (int i = 0; i < 4; i++) a[i] = As[kk][ty*4 + i];
#pragma unroll
            for (int j = 0; j < 4; j++) b[j] = Bs[kk][tx*4 + j];
#pragma unroll
            for (int i = 0; i < 4; i++)
#pragma unroll
                for (int j = 0; j < 4; j++) acc[i][j] += a[i] * b[j];
        }
        __syncthreads();
    }

#pragma unroll
    for (int i = 0; i < 4; i++)
#pragma unroll
        for (int j = 0; j < 4; j++) Ls[ty*4 + i][tx*4 + j] = acc[i][j];
    __syncthreads();

    if (tid < 64) {
        int   sel[TOPK];
        float sv [TOPK];
        unsigned long long mask = 0ull;
#pragma unroll
        for (int k = 0; k < TOPK; k++) {
            float best = -1e30f;
            int   be   = 0;
            for (int e = 0; e < NEXP; e++) {
                if ((mask >> e) & 1ull) continue;
                float v = Ls[tid][e];
                if (v > best) { best = v; be = e; }
            }
            mask |= (1ull << be);
            sel[k] = be;
            sv[k]  = best;
        }
        float mx = sv[0];
        float s  = 0.f;
#pragma unroll
        for (int k = 0; k < TOPK; k++) { sv[k] = expf(sv[k] - mx); s += sv[k]; }
        float inv = 1.f / s;
#pragma unroll
        for (int k = 0; k < TOPK; k++) {
            int e   = sel[k];
            int pos = atomicAdd(&g_count[e], 1);
            g_entry[e * T_TOK + pos] = (t0 + tid) * TOPK + k;
            g_wt   [e * T_TOK + pos] = sv[k] * inv;
        }
    }
}

// ---------------- kernel 2: gate+up HMMA GEMM, fused SwiGLU ----------------
// BM=128 gathered tokens, BN=64 (both gate & up), BK=32, fp16 hi/lo split.
// Warp strips of 32 rows beyond cnt skip all LDSM/MMA work (waste cut).
#define GU_BUF  (2 * A_BYTES + 4 * B_BYTES)          // 38912
#define GU_SMEM (1024 + 2 * GU_BUF)                  // 78848

__global__ __launch_bounds__(256, 1)
void gateup_mma(const float* __restrict__ x,
                const float* __restrict__ wg,
                const float* __restrict__ wu) {
    extern __shared__ char smem[];
    const int e   = blockIdx.z;
    const int cnt = g_count[e];
    const int m0  = blockIdx.y * 128;
    if (m0 >= cnt) return;
    const int n0  = blockIdx.x * 64;
    const int tid  = threadIdx.x;
    const int wid  = tid >> 5;
    const int lane = tid & 31;

    const uint32_t sb = smem_u32(smem);
    int*   sEnt = (int*)smem;
    float* sW   = (float*)(smem + 512);

    if (tid < 128) {
        int mi = m0 + tid;
        if (mi < cnt) { sEnt[tid] = g_entry[e * T_TOK + mi]; sW[tid] = g_wt[e * T_TOK + mi]; }
        else          { sEnt[tid] = -1;                      sW[tid] = 0.f; }
    }
    __syncthreads();

    // loader mappings
    const int arow = tid >> 1, akh = (tid & 1) * 16;
    const int aent = sEnt[arow];
    const float* ax = x + (size_t)(aent >= 0 ? (aent >> 3) : 0) * HDIM + akh;
    const int brow = tid >> 3, bcol = (tid & 7) * 8;
    const float* pg = wg + (size_t)e * HDIM * IDIM + n0 + bcol;
    const float* pu = wu + (size_t)e * HDIM * IDIM + n0 + bcol;

    float4 fA[4], fG[2], fU[2];
    auto loadRegs = [&](int k0) {
        if (aent >= 0) {
            fA[0] = *(const float4*)(ax + k0);
            fA[1] = *(const float4*)(ax + k0 + 4);
            fA[2] = *(const float4*)(ax + k0 + 8);
            fA[3] = *(const float4*)(ax + k0 + 12);
        } else {
            fA[0] = make_float4(0.f, 0.f, 0.f, 0.f);
            fA[1] = fA[2] = fA[3] = fA[0];
        }
        const float* gp = pg + (size_t)(k0 + brow) * IDIM;
        const float* up = pu + (size_t)(k0 + brow) * IDIM;
        fG[0] = *(const float4*)gp; fG[1] = *(const float4*)(gp + 4);
        fU[0] = *(const float4*)up; fU[1] = *(const float4*)(up + 4);
    };

    auto stsRegs = [&](int b) {
        const uint32_t base = sb + 1024 + b * GU_BUF;
        const uint32_t Ah = base, Al = base + A_BYTES;
        const uint32_t Bgh = base + 2 * A_BYTES, Bgl = Bgh + B_BYTES;
        const uint32_t Buh = Bgl + B_BYTES,      Bul = Buh + B_BYTES;
        uint32_t h0, h1, l0, l1, h2, h3, l2, l3;
        const uint32_t offA = arow * 80 + akh * 2;
        cvt4h(fA[0], h0, h1, l0, l1); cvt4h(fA[1], h2, h3, l2, l3);
        sts128(Ah + offA, h0, h1, h2, h3); sts128(Al + offA, l0, l1, l2, l3);
        cvt4h(fA[2], h0, h1, l0, l1); cvt4h(fA[3], h2, h3, l2, l3);
        sts128(Ah + offA + 16, h0, h1, h2, h3); sts128(Al + offA + 16, l0, l1, l2, l3);
        const uint32_t offB = brow * 144 + bcol * 2;
        cvt4h(fG[0], h0, h1, l0, l1); cvt4h(fG[1], h2, h3, l2, l3);
        sts128(Bgh + offB, h0, h1, h2, h3); sts128(Bgl + offB, l0, l1, l2, l3);
        cvt4h(fU[0], h0, h1, l0, l1); cvt4h(fU[1], h2, h3, l2, l3);
        sts128(Buh + offB, h0, h1, h2, h3); sts128(Bul + offB, l0, l1, l2, l3);
    };

    const int wm = wid >> 1, wn = wid & 1;
    const bool strip_active = (m0 + wm * 32) < cnt;   // 32-row strip granularity
    float accg[2][4][4], accu[2][4][4];
#pragma unroll
    for (int i = 0; i < 2; i++)
#pragma unroll
        for (int j = 0; j < 4; j++)
#pragma unroll
            for (int q = 0; q < 4; q++) { accg[i][j][q] = 0.f; accu[i][j][q] = 0.f; }

    auto compute = [&](int b) {
        const uint32_t base = sb + 1024 + b * GU_BUF;
        const uint32_t Ah = base, Al = base + A_BYTES;
        const uint32_t Bgh = base + 2 * A_BYTES, Bgl = Bgh + B_BYTES;
        const uint32_t Buh = Bgl + B_BYTES,      Bul = Buh + B_BYTES;
#pragma unroll
        for (int kk = 0; kk < 2; kk++) {
            uint32_t ah[2][4], al[2][4];
            const uint32_t acol = (kk * 16 + (lane >> 4) * 8) * 2;
#pragma unroll
            for (int i = 0; i < 2; i++) {
                uint32_t ra = (wm * 32 + i * 16 + (lane & 15)) * 80 + acol;
                ldsm4(ah[i][0], ah[i][1], ah[i][2], ah[i][3], Ah + ra);
                ldsm4(al[i][0], al[i][1], al[i][2], al[i][3], Al + ra);
            }
            const uint32_t brow_ = kk * 16 + ((lane >> 3) & 1) * 8 + (lane & 7);
#pragma unroll
            for (int hf = 0; hf < 2; hf++) {
                const uint32_t rb = brow_ * 144 + (wn * 32 + hf * 16 + (lane >> 4) * 8) * 2;
                uint32_t g0, g1, g2, g3, gl0, gl1, gl2, gl3;
                ldsm4t(g0, g1, g2, g3, Bgh + rb);
                ldsm4t(gl0, gl1, gl2, gl3, Bgl + rb);
#pragma unroll
                for (int i = 0; i < 2; i++) {
                    float* c0 = accg[i][hf * 2 + 0];
                    float* c1 = accg[i][hf * 2 + 1];
                    mma_h(c0[0], c0[1], c0[2], c0[3], ah[i][0], ah[i][1], ah[i][2], ah[i][3], g0, g1);
                    mma_h(c0[0], c0[1], c0[2], c0[3], ah[i][0], ah[i][1], ah[i][2], ah[i][3], gl0, gl1);
                    mma_h(c0[0], c0[1], c0[2], c0[3], al[i][0], al[i][1], al[i][2], al[i][3], g0, g1);
                    mma_h(c1[0], c1[1], c1[2], c1[3], ah[i][0], ah[i][1], ah[i][2], ah[i][3], g2, g3);
                    mma_h(c1[0], c1[1], c1[2], c1[3], ah[i][0], ah[i][1], ah[i][2], ah[i][3], gl2, gl3);
                    mma_h(c1[0], c1[1], c1[2], c1[3], al[i][0], al[i][1], al[i][2], al[i][3], g2, g3);
                }
                uint32_t u0, u1, u2, u3, ul0, ul1, ul2, ul3;
                ldsm4t(u0, u1, u2, u3, Buh + rb);
                ldsm4t(ul0, ul1, ul2, ul3, Bul + rb);
#pragma unroll
                for (int i = 0; i < 2; i++) {
                    float* c0 = accu[i][hf * 2 + 0];
                    float* c1 = accu[i][hf * 2 + 1];
                    mma_h(c0[0], c0[1], c0[2], c0[3], ah[i][0], ah[i][1], ah[i][2], ah[i][3], u0, u1);
                    mma_h(c0[0], c0[1], c0[2], c0[3], ah[i][0], ah[i][1], ah[i][2], ah[i][3], ul0, ul1);
                    mma_h(c0[0], c0[1], c0[2], c0[3], al[i][0], al[i][1], al[i][2], al[i][3], u0, u1);
                    mma_h(c1[0], c1[1], c1[2], c1[3], ah[i][0], ah[i][1], ah[i][2], ah[i][3], u2, u3);
                    mma_h(c1[0], c1[1], c1[2], c1[3], ah[i][0], ah[i][1], ah[i][2], ah[i][3], ul2, ul3);
                    mma_h(c1[0], c1[1], c1[2], c1[3], al[i][0], al[i][1], al[i][2], al[i][3], u2, u3);
                }
            }
        }
    };

    loadRegs(0);
    stsRegs(0);
    __syncthreads();

    const int C = HDIM / 32;
    for (int c = 0; c < C; c++) {
        if (c + 1 < C) loadRegs((c + 1) * 32);
        if (strip_active) compute(c & 1);
        if (c + 1 < C) { stsRegs((c + 1) & 1); __syncthreads(); }
    }

    // epilogue: silu(g)*u*w -> fp16 hi/lo planes
    if (strip_active) {
#pragma unroll
        for (int i = 0; i < 2; i++)
#pragma unroll
            for (int nt = 0; nt < 4; nt++) {
                const int r    = wm * 32 + i * 16 + (lane >> 2);
                const int cof  = n0 + wn * 32 + nt * 8 + (lane & 3) * 2;
#pragma unroll
                for (int half_ = 0; half_ < 2; half_++) {
                    const int rr  = r + half_ * 8;
                    const int ent = sEnt[rr];
                    if (ent >= 0) {
                        const float w = sW[rr];
                        float g0 = accg[i][nt][half_ * 2 + 0], g1 = accg[i][nt][half_ * 2 + 1];
                        float u0 = accu[i][nt][half_ * 2 + 0], u1 = accu[i][nt][half_ * 2 + 1];
                        float v0 = g0 / (1.f + expf(-g0)) * u0 * w;
                        float v1 = g1 / (1.f + expf(-g1)) * u1 * w;
                        __half h0 = __float2half_rn(v0), h1 = __float2half_rn(v1);
                        __half l0 = __float2half_rn(v0 - __half2float(h0));
                        __half l1 = __float2half_rn(v1 - __half2float(h1));
                        size_t off = (size_t)ent * IDIM + cof;
                        *(__half2*)(g_act_h + off) = __halves2half2(h0, h1);
                        *(__half2*)(g_act_l + off) = __halves2half2(l0, l1);
                    }
                }
            }
    }
}

// ---------------- kernel 3: down HMMA GEMM, atomic scatter ----------------
#define DN_BUF  (2 * A_BYTES + 2 * B_BYTES)          // 29696
#define DN_SMEM (1024 + 2 * DN_BUF)                  // 60416

__global__ __launch_bounds__(256, 1)
void down_mma(const float* __restrict__ wd, float* __restrict__ out) {
    extern __shared__ char smem[];
    const int e   = blockIdx.z;
    const int cnt = g_count[e];
    const int m0  = blockIdx.y * 128;
    if (m0 >= cnt) return;
    const int n0  = blockIdx.x * 64;
    const int tid  = threadIdx.x;
    const int wid  = tid >> 5;
    const int lane = tid & 31;

    const uint32_t sb = smem_u32(smem);
    int* sEnt = (int*)smem;

    if (tid < 128) {
        int mi = m0 + tid;
        sEnt[tid] = (mi < cnt) ? g_entry[e * T_TOK + mi] : -1;
    }
    __syncthreads();

    const int arow = tid >> 1, akh = (tid & 1) * 16;
    const int aent = sEnt[arow];
    const __half* axh = g_act_h + (size_t)(aent >= 0 ? aent : 0) * IDIM + akh;
    const __half* axl = g_act_l + (size_t)(aent >= 0 ? aent : 0) * IDIM + akh;
    const int brow = tid >> 3, bcol = (tid & 7) * 8;
    const float* pb = wd + (size_t)e * IDIM * HDIM + n0 + bcol;

    uint4 hA0, hA1, lA0, lA1;
    float4 fB[2];
    auto loadRegs = [&](int k0) {
        if (aent >= 0) {
            hA0 = *(const uint4*)(axh + k0);
            hA1 = *(const uint4*)(axh + k0 + 8);
            lA0 = *(const uint4*)(axl + k0);
            lA1 = *(const uint4*)(axl + k0 + 8);
        } else {
            hA0 = make_uint4(0u, 0u, 0u, 0u);
            hA1 = lA0 = lA1 = hA0;
        }
        const float* bp = pb + (size_t)(k0 + brow) * HDIM;
        fB[0] = *(const float4*)bp; fB[1] = *(const float4*)(bp + 4);
    };

    auto stsRegs = [&](int b) {
        const uint32_t base = sb + 1024 + b * DN_BUF;
        const uint32_t Ah = base, Al = base + A_BYTES;
        const uint32_t Bh = base + 2 * A_BYTES, Bl = Bh + B_BYTES;
        const uint32_t offA = arow * 80 + akh * 2;
        sts128(Ah + offA,      hA0.x, hA0.y, hA0.z, hA0.w);
        sts128(Ah + offA + 16, hA1.x, hA1.y, hA1.z, hA1.w);
        sts128(Al + offA,      lA0.x, lA0.y, lA0.z, lA0.w);
        sts128(Al + offA + 16, lA1.x, lA1.y, lA1.z, lA1.w);
        uint32_t h0, h1, l0, l1, h2, h3, l2, l3;
        const uint32_t offB = brow * 144 + bcol * 2;
        cvt4h(fB[0], h0, h1, l0, l1); cvt4h(fB[1], h2, h3, l2, l3);
        sts128(Bh + offB, h0, h1, h2, h3); sts128(Bl + offB, l0, l1, l2, l3);
    };

    const int wm = wid >> 1, wn = wid & 1;
    const bool strip_active = (m0 + wm * 32) < cnt;
    float acc[2][4][4];
#pragma unroll
    for (int i = 0; i < 2; i++)
#pragma unroll
        for (int j = 0; j < 4; j++)
#pragma unroll
            for (int q = 0; q < 4; q++) acc[i][j][q] = 0.f;

    auto compute = [&](int b) {
        const uint32_t base = sb + 1024 + b * DN_BUF;
        const uint32_t Ah = base, Al = base + A_BYTES;
        const uint32_t Bh = base + 2 * A_BYTES, Bl = Bh + B_BYTES;
#pragma unroll
        for (int kk = 0; kk < 2; kk++) {
            uint32_t ah[2][4], al[2][4];
            const uint32_t acol = (kk * 16 + (lane >> 4) * 8) * 2;
#pragma unroll
            for (int i = 0; i < 2; i++) {
                uint32_t ra = (wm * 32 + i * 16 + (lane & 15)) * 80 + acol;
                ldsm4(ah[i][0], ah[i][1], ah[i][2], ah[i][3], Ah + ra);
                ldsm4(al[i][0], al[i][1], al[i][2], al[i][3], Al + ra);
            }
            const uint32_t brow_ = kk * 16 + ((lane >> 3) & 1) * 8 + (lane & 7);
#pragma unroll
            for (int hf = 0; hf < 2; hf++) {
                const uint32_t rb = brow_ * 144 + (wn * 32 + hf * 16 + (lane >> 4) * 8) * 2;
                uint32_t b0, b1, b2, b3, bl0, bl1, bl2, bl3;
                ldsm4t(b0, b1, b2, b3, Bh + rb);
                ldsm4t(bl0, bl1, bl2, bl3, Bl + rb);
#pragma unroll
                for (int i = 0; i < 2; i++) {
                    float* c0 = acc[i][hf * 2 + 0];
                    float* c1 = acc[i][hf * 2 + 1];
                    mma_h(c0[0], c0[1], c0[2], c0[3], ah[i][0], ah[i][1], ah[i][2], ah[i][3], b0, b1);
                    mma_h(c0[0], c0[1], c0[2], c0[3], ah[i][0], ah[i][1], ah[i][2], ah[i][3], bl0, bl1);
                    mma_h(c0[0], c0[1], c0[2], c0[3], al[i][0], al[i][1], al[i][2], al[i][3], b0, b1);
                    mma_h(c1[0], c1[1], c1[2], c1[3], ah[i][0], ah[i][1], ah[i][2], ah[i][3], b2, b3);
                    mma_h(c1[0], c1[1], c1[2], c1[3], ah[i][0], ah[i][1], ah[i][2], ah[i][3], bl2, bl3);
                    mma_h(c1[0], c1[1], c1[2], c1[3], al[i][0], al[i][1], al[i][2], al[i][3], b2, b3);
                }
            }
        }
    };

    loadRegs(0);
    stsRegs(0);
    __syncthreads();

    const int C = IDIM / 32;
    for (int c = 0; c < C; c++) {
        if (c + 1 < C) loadRegs((c + 1) * 32);
        if (strip_active) compute(c & 1);
        if (c + 1 < C) { stsRegs((c + 1) & 1); __syncthreads(); }
    }

    if (strip_active) {
#pragma unroll
        for (int i = 0; i < 2; i++)
#pragma unroll
            for (int nt = 0; nt < 4; nt++) {
                const int r   = wm * 32 + i * 16 + (lane >> 2);
                const int cof = n0 + wn * 32 + nt * 8 + (lane & 3) * 2;
#pragma unroll
                for (int half_ = 0; half_ < 2; half_++) {
                    const int rr  = r + half_ * 8;
                    const int ent = sEnt[rr];
                    if (ent >= 0) {
                        float* dst = out + (size_t)(ent >> 3) * HDIM + cof;
                        atomicAdd(dst,     acc[i][nt][half_ * 2 + 0]);
                        atomicAdd(dst + 1, acc[i][nt][half_ * 2 + 1]);
                    }
                }
            }
    }
}

// ---------------- launch ----------------
extern "C" void kernel_launch(void* const* d_in, const int* in_sizes, int n_in,
                              void* d_out, int out_size) {
    const float* x  = (const float*)d_in[0];
    const float* gw = (const float*)d_in[1];
    const float* wg = (const float*)d_in[2];
    const float* wu = (const float*)d_in[3];
    const float* wd = (const float*)d_in[4];
    float* out = (float*)d_out;

    static int smem_set = 0;
    if (!smem_set) {
        cudaFuncSetAttribute(gateup_mma, cudaFuncAttributeMaxDynamicSharedMemorySize, GU_SMEM);
        cudaFuncSetAttribute(down_mma,   cudaFuncAttributeMaxDynamicSharedMemorySize, DN_SMEM);
        smem_set = 1;
    }

    cudaMemsetAsync(out, 0, (size_t)T_TOK * HDIM * sizeof(float));
    zero_counts_kernel<<<1, 64>>>();
    router_kernel<<<T_TOK / 64, 256>>>(x, gw);

    dim3 gu_grid(IDIM / 64, T_TOK / 128, NEXP);
    gateup_mma<<<gu_grid, 256, GU_SMEM>>>(x, wg, wu);

    dim3 dn_grid(HDIM / 64, T_TOK / 128, NEXP);
    down_mma<<<dn_grid, 256, DN_SMEM>>>(wd, out);
}

// round 5
// speedup vs baseline: 2.3833x; 1.2337x over previous
#include <cuda_runtime.h>
#include <cuda_fp16.h>
#include <math.h>
#include <stdint.h>

#define T_TOK 1024
#define HDIM  2048
#define NEXP  64
#define IDIM  768
#define TOPK  8

// ---------------- device scratch ----------------
__device__ int    g_count[NEXP];
__device__ int    g_entry[NEXP * T_TOK];           // token*8 + slot
__device__ float  g_wt   [NEXP * T_TOK];
__device__ __half g_act_h[T_TOK * TOPK * IDIM];    // fp16 hi plane of silu(g)*u*w
__device__ __half g_act_l[T_TOK * TOPK * IDIM];    // fp16 lo plane

// ---------------- helpers ----------------
__device__ __forceinline__ uint32_t smem_u32(const void* p) {
    uint32_t a;
    asm("{ .reg .u64 t; cvta.to.shared.u64 t, %1; cvt.u32.u64 %0, t; }" : "=r"(a) : "l"(p));
    return a;
}
__device__ __forceinline__ void sts128(uint32_t a, uint32_t x, uint32_t y, uint32_t z, uint32_t w) {
    asm volatile("st.shared.v4.b32 [%0], {%1,%2,%3,%4};" :: "r"(a), "r"(x), "r"(y), "r"(z), "r"(w));
}
__device__ __forceinline__ void ldsm4(uint32_t& r0, uint32_t& r1, uint32_t& r2, uint32_t& r3, uint32_t a) {
    asm volatile("ldmatrix.sync.aligned.m8n8.x4.shared.b16 {%0,%1,%2,%3}, [%4];"
                 : "=r"(r0), "=r"(r1), "=r"(r2), "=r"(r3) : "r"(a));
}
__device__ __forceinline__ void ldsm4t(uint32_t& r0, uint32_t& r1, uint32_t& r2, uint32_t& r3, uint32_t a) {
    asm volatile("ldmatrix.sync.aligned.m8n8.x4.trans.shared.b16 {%0,%1,%2,%3}, [%4];"
                 : "=r"(r0), "=r"(r1), "=r"(r2), "=r"(r3) : "r"(a));
}
__device__ __forceinline__ void mma_h(float& c0, float& c1, float& c2, float& c3,
                                      uint32_t a0, uint32_t a1, uint32_t a2, uint32_t a3,
                                      uint32_t b0, uint32_t b1) {
    asm volatile("mma.sync.aligned.m16n8k16.row.col.f32.f16.f16.f32 "
                 "{%0,%1,%2,%3},{%4,%5,%6,%7},{%8,%9},{%0,%1,%2,%3};"
                 : "+f"(c0), "+f"(c1), "+f"(c2), "+f"(c3)
                 : "r"(a0), "r"(a1), "r"(a2), "r"(a3), "r"(b0), "r"(b1));
}
__device__ __forceinline__ uint32_t packh(__half lo, __half hi) {
    return (uint32_t)__half_as_ushort(lo) | ((uint32_t)__half_as_ushort(hi) << 16);
}
// split fp32x4 -> fp16 hi (2 regs) + fp16 lo (2 regs)
__device__ __forceinline__ void cvt4h(float4 f, uint32_t& h0, uint32_t& h1,
                                      uint32_t& l0, uint32_t& l1) {
    __half ax = __float2half_rn(f.x), ay = __float2half_rn(f.y);
    __half az = __float2half_rn(f.z), aw = __float2half_rn(f.w);
    __half bx = __float2half_rn(f.x - __half2float(ax));
    __half by = __float2half_rn(f.y - __half2float(ay));
    __half bz = __float2half_rn(f.z - __half2float(az));
    __half bw = __float2half_rn(f.w - __half2float(aw));
    h0 = packh(ax, ay); h1 = packh(az, aw);
    l0 = packh(bx, by); l1 = packh(bz, bw);
}
// single-plane fp16 convert: fp32x4 -> 2 packed regs
__device__ __forceinline__ void cvt2h(float4 f, uint32_t& h0, uint32_t& h1) {
    __half2 a = __floats2half2_rn(f.x, f.y);
    __half2 b = __floats2half2_rn(f.z, f.w);
    h0 = *(uint32_t*)&a; h1 = *(uint32_t*)&b;
}

// smem geometry (fp16 elems): A tile 128x32, row stride 40 (80B, conflict-free)
//                             B tile  32x64, row stride 72 (144B, conflict-free)
#define A_BYTES  10240   // 128*40*2
#define B1_BYTES 4608    // 32*72*2 (single fp16 plane)

// ---------------- kernel 0: reset counters ----------------
__global__ void zero_counts_kernel() {
    if (threadIdx.x < NEXP) g_count[threadIdx.x] = 0;
}

// ---------------- kernel 1: router GEMM + top-8 + bucket scatter ----------------
// 64 blocks x 16 tokens. 256 threads = 16x16; thread (ty,tx) -> row ty, experts tx*4..+3.
__global__ __launch_bounds__(256)
void router_kernel(const float* __restrict__ x, const float* __restrict__ gw) {
    __shared__ float As[16][17];
    __shared__ float Bs[16][68];
    __shared__ float Ls[16][68];

    const int t0  = blockIdx.x * 16;
    const int tid = threadIdx.x;
    const int tx  = tid & 15;
    const int ty  = tid >> 4;

    // loaders
    const int am = tid >> 4, ak = tid & 15;           // A: row, k within chunk
    const int be = tid & 63, bk4 = (tid >> 6) * 4;    // B: expert, k group

    float acc[4] = {0.f, 0.f, 0.f, 0.f};

    for (int k0 = 0; k0 < HDIM; k0 += 16) {
        As[ak][am] = x[(size_t)(t0 + am) * HDIM + k0 + ak];
        float4 bv = *(const float4*)(gw + (size_t)be * HDIM + k0 + bk4);
        Bs[bk4 + 0][be] = bv.x; Bs[bk4 + 1][be] = bv.y;
        Bs[bk4 + 2][be] = bv.z; Bs[bk4 + 3][be] = bv.w;
        __syncthreads();
#pragma unroll
        for (int kk = 0; kk < 16; kk++) {
            float a = As[kk][ty];
#pragma unroll
            for (int j = 0; j < 4; j++) acc[j] += a * Bs[kk][tx * 4 + j];
        }
        __syncthreads();
    }

#pragma unroll
    for (int j = 0; j < 4; j++) Ls[ty][tx * 4 + j] = acc[j];
    __syncthreads();

    if (tid < 16) {
        int   sel[TOPK];
        float sv [TOPK];
        unsigned long long mask = 0ull;
#pragma unroll
        for (int k = 0; k < TOPK; k++) {
            float best = -1e30f;
            int   be_  = 0;
            for (int e = 0; e < NEXP; e++) {
                if ((mask >> e) & 1ull) continue;
                float v = Ls[tid][e];
                if (v > best) { best = v; be_ = e; }
            }
            mask |= (1ull << be_);
            sel[k] = be_;
            sv[k]  = best;
        }
        float mx = sv[0];
        float s  = 0.f;
#pragma unroll
        for (int k = 0; k < TOPK; k++) { sv[k] = expf(sv[k] - mx); s += sv[k]; }
        float inv = 1.f / s;
#pragma unroll
        for (int k = 0; k < TOPK; k++) {
            int e   = sel[k];
            int pos = atomicAdd(&g_count[e], 1);
            g_entry[e * T_TOK + pos] = (t0 + tid) * TOPK + k;
            g_wt   [e * T_TOK + pos] = sv[k] * inv;
        }
    }
}

// ---------------- kernel 2: gate+up HMMA GEMM, fused SwiGLU ----------------
// BM=128 gathered tokens, BN=64 (both gate & up), BK=32.
// A split fp16 hi/lo (2 MMA terms); B single fp16 plane.
#define GU_BUF  (2 * A_BYTES + 2 * B1_BYTES)         // 29696
#define GU_SMEM (1024 + 2 * GU_BUF)                  // 60416

__global__ __launch_bounds__(256, 1)
void gateup_mma(const float* __restrict__ x,
                const float* __restrict__ wg,
                const float* __restrict__ wu) {
    extern __shared__ char smem[];
    const int e   = blockIdx.z;
    const int cnt = g_count[e];
    const int m0  = blockIdx.y * 128;
    if (m0 >= cnt) return;
    const int n0  = blockIdx.x * 64;
    const int tid  = threadIdx.x;
    const int wid  = tid >> 5;
    const int lane = tid & 31;

    const uint32_t sb = smem_u32(smem);
    int*   sEnt = (int*)smem;
    float* sW   = (float*)(smem + 512);

    if (tid < 128) {
        int mi = m0 + tid;
        if (mi < cnt) { sEnt[tid] = g_entry[e * T_TOK + mi]; sW[tid] = g_wt[e * T_TOK + mi]; }
        else          { sEnt[tid] = -1;                      sW[tid] = 0.f; }
    }
    __syncthreads();

    const int wm = wid >> 1, wn = wid & 1;
    const bool strip_active = (m0 + wm * 32) < cnt;   // fill strip == compute strip (tid>>6)

    // loader mappings
    const int arow = tid >> 1, akh = (tid & 1) * 16;
    const int aent = sEnt[arow];
    const float* ax = x + (size_t)(aent >= 0 ? (aent >> 3) : 0) * HDIM + akh;
    const int brow = tid >> 3, bcol = (tid & 7) * 8;
    const float* pg = wg + (size_t)e * HDIM * IDIM + n0 + bcol;
    const float* pu = wu + (size_t)e * HDIM * IDIM + n0 + bcol;
    const bool aload = strip_active && (aent >= 0);

    float4 fA[4], fG[2], fU[2];
    auto loadRegs = [&](int k0) {
        if (aload) {
            fA[0] = *(const float4*)(ax + k0);
            fA[1] = *(const float4*)(ax + k0 + 4);
            fA[2] = *(const float4*)(ax + k0 + 8);
            fA[3] = *(const float4*)(ax + k0 + 12);
        }
        const float* gp = pg + (size_t)(k0 + brow) * IDIM;
        const float* up = pu + (size_t)(k0 + brow) * IDIM;
        fG[0] = *(const float4*)gp; fG[1] = *(const float4*)(gp + 4);
        fU[0] = *(const float4*)up; fU[1] = *(const float4*)(up + 4);
    };

    auto stsRegs = [&](int b) {
        const uint32_t base = sb + 1024 + b * GU_BUF;
        const uint32_t Ah = base, Al = base + A_BYTES;
        const uint32_t Bg = base + 2 * A_BYTES, Bu = Bg + B1_BYTES;
        uint32_t h0, h1, l0, l1, h2, h3, l2, l3;
        if (strip_active) {
            if (!aload) {
                fA[0] = make_float4(0.f, 0.f, 0.f, 0.f);
                fA[1] = fA[2] = fA[3] = fA[0];
            }
            const uint32_t offA = arow * 80 + akh * 2;
            cvt4h(fA[0], h0, h1, l0, l1); cvt4h(fA[1], h2, h3, l2, l3);
            sts128(Ah + offA, h0, h1, h2, h3); sts128(Al + offA, l0, l1, l2, l3);
            cvt4h(fA[2], h0, h1, l0, l1); cvt4h(fA[3], h2, h3, l2, l3);
            sts128(Ah + offA + 16, h0, h1, h2, h3); sts128(Al + offA + 16, l0, l1, l2, l3);
        }
        const uint32_t offB = brow * 144 + bcol * 2;
        cvt2h(fG[0], h0, h1); cvt2h(fG[1], h2, h3);
        sts128(Bg + offB, h0, h1, h2, h3);
        cvt2h(fU[0], h0, h1); cvt2h(fU[1], h2, h3);
        sts128(Bu + offB, h0, h1, h2, h3);
    };

    float accg[2][4][4], accu[2][4][4];
#pragma unroll
    for (int i = 0; i < 2; i++)
#pragma unroll
        for (int j = 0; j < 4; j++)
#pragma unroll
            for (int q = 0; q < 4; q++) { accg[i][j][q] = 0.f; accu[i][j][q] = 0.f; }

    auto compute = [&](int b) {
        const uint32_t base = sb + 1024 + b * GU_BUF;
        const uint32_t Ah = base, Al = base + A_BYTES;
        const uint32_t Bg = base + 2 * A_BYTES, Bu = Bg + B1_BYTES;
#pragma unroll
        for (int kk = 0; kk < 2; kk++) {
            uint32_t ah[2][4], al[2][4];
            const uint32_t acol = (kk * 16 + (lane >> 4) * 8) * 2;
#pragma unroll
            for (int i = 0; i < 2; i++) {
                uint32_t ra = (wm * 32 + i * 16 + (lane & 15)) * 80 + acol;
                ldsm4(ah[i][0], ah[i][1], ah[i][2], ah[i][3], Ah + ra);
                ldsm4(al[i][0], al[i][1], al[i][2], al[i][3], Al + ra);
            }
            const uint32_t brow_ = kk * 16 + ((lane >> 3) & 1) * 8 + (lane & 7);
#pragma unroll
            for (int hf = 0; hf < 2; hf++) {
                const uint32_t rb = brow_ * 144 + (wn * 32 + hf * 16 + (lane >> 4) * 8) * 2;
                uint32_t g0, g1, g2, g3;
                ldsm4t(g0, g1, g2, g3, Bg + rb);
#pragma unroll
                for (int i = 0; i < 2; i++) {
                    float* c0 = accg[i][hf * 2 + 0];
                    float* c1 = accg[i][hf * 2 + 1];
                    mma_h(c0[0], c0[1], c0[2], c0[3], ah[i][0], ah[i][1], ah[i][2], ah[i][3], g0, g1);
                    mma_h(c0[0], c0[1], c0[2], c0[3], al[i][0], al[i][1], al[i][2], al[i][3], g0, g1);
                    mma_h(c1[0], c1[1], c1[2], c1[3], ah[i][0], ah[i][1], ah[i][2], ah[i][3], g2, g3);
                    mma_h(c1[0], c1[1], c1[2], c1[3], al[i][0], al[i][1], al[i][2], al[i][3], g2, g3);
                }
                uint32_t u0, u1, u2, u3;
                ldsm4t(u0, u1, u2, u3, Bu + rb);
#pragma unroll
                for (int i = 0; i < 2; i++) {
                    float* c0 = accu[i][hf * 2 + 0];
                    float* c1 = accu[i][hf * 2 + 1];
                    mma_h(c0[0], c0[1], c0[2], c0[3], ah[i][0], ah[i][1], ah[i][2], ah[i][3], u0, u1);
                    mma_h(c0[0], c0[1], c0[2], c0[3], al[i][0], al[i][1], al[i][2], al[i][3], u0, u1);
                    mma_h(c1[0], c1[1], c1[2], c1[3], ah[i][0], ah[i][1], ah[i][2], ah[i][3], u2, u3);
                    mma_h(c1[0], c1[1], c1[2], c1[3], al[i][0], al[i][1], al[i][2], al[i][3], u2, u3);
                }
            }
        }
    };

    loadRegs(0);
    stsRegs(0);
    __syncthreads();

    const int C = HDIM / 32;
    for (int c = 0; c < C; c++) {
        if (c + 1 < C) loadRegs((c + 1) * 32);
        if (strip_active) compute(c & 1);
        if (c + 1 < C) { stsRegs((c + 1) & 1); __syncthreads(); }
    }

    // epilogue: silu(g)*u*w -> fp16 hi/lo planes
    if (strip_active) {
#pragma unroll
        for (int i = 0; i < 2; i++)
#pragma unroll
            for (int nt = 0; nt < 4; nt++) {
                const int r    = wm * 32 + i * 16 + (lane >> 2);
                const int cof  = n0 + wn * 32 + nt * 8 + (lane & 3) * 2;
#pragma unroll
                for (int half_ = 0; half_ < 2; half_++) {
                    const int rr  = r + half_ * 8;
                    const int ent = sEnt[rr];
                    if (ent >= 0) {
                        const float w = sW[rr];
                        float g0 = accg[i][nt][half_ * 2 + 0], g1 = accg[i][nt][half_ * 2 + 1];
                        float u0 = accu[i][nt][half_ * 2 + 0], u1 = accu[i][nt][half_ * 2 + 1];
                        float v0 = g0 / (1.f + expf(-g0)) * u0 * w;
                        float v1 = g1 / (1.f + expf(-g1)) * u1 * w;
                        __half h0 = __float2half_rn(v0), h1 = __float2half_rn(v1);
                        __half l0 = __float2half_rn(v0 - __half2float(h0));
                        __half l1 = __float2half_rn(v1 - __half2float(h1));
                        size_t off = (size_t)ent * IDIM + cof;
                        *(__half2*)(g_act_h + off) = __halves2half2(h0, h1);
                        *(__half2*)(g_act_l + off) = __halves2half2(l0, l1);
                    }
                }
            }
    }
}

// ---------------- kernel 3: down HMMA GEMM, atomic scatter ----------------
#define DN_BUF  (2 * A_BYTES + B1_BYTES)             // 25088
#define DN_SMEM (1024 + 2 * DN_BUF)                  // 51200

__global__ __launch_bounds__(256, 1)
void down_mma(const float* __restrict__ wd, float* __restrict__ out) {
    extern __shared__ char smem[];
    const int e   = blockIdx.z;
    const int cnt = g_count[e];
    const int m0  = blockIdx.y * 128;
    if (m0 >= cnt) return;
    const int n0  = blockIdx.x * 64;
    const int tid  = threadIdx.x;
    const int wid  = tid >> 5;
    const int lane = tid & 31;

    const uint32_t sb = smem_u32(smem);
    int* sEnt = (int*)smem;

    if (tid < 128) {
        int mi = m0 + tid;
        sEnt[tid] = (mi < cnt) ? g_entry[e * T_TOK + mi] : -1;
    }
    __syncthreads();

    const int wm = wid >> 1, wn = wid & 1;
    const bool strip_active = (m0 + wm * 32) < cnt;

    const int arow = tid >> 1, akh = (tid & 1) * 16;
    const int aent = sEnt[arow];
    const __half* axh = g_act_h + (size_t)(aent >= 0 ? aent : 0) * IDIM + akh;
    const __half* axl = g_act_l + (size_t)(aent >= 0 ? aent : 0) * IDIM + akh;
    const int brow = tid >> 3, bcol = (tid & 7) * 8;
    const float* pb = wd + (size_t)e * IDIM * HDIM + n0 + bcol;
    const bool aload = strip_active && (aent >= 0);

    uint4 hA0, hA1, lA0, lA1;
    float4 fB[2];
    auto loadRegs = [&](int k0) {
        if (aload) {
            hA0 = *(const uint4*)(axh + k0);
            hA1 = *(const uint4*)(axh + k0 + 8);
            lA0 = *(const uint4*)(axl + k0);
            lA1 = *(const uint4*)(axl + k0 + 8);
        }
        const float* bp = pb + (size_t)(k0 + brow) * HDIM;
        fB[0] = *(const float4*)bp; fB[1] = *(const float4*)(bp + 4);
    };

    auto stsRegs = [&](int b) {
        const uint32_t base = sb + 1024 + b * DN_BUF;
        const uint32_t Ah = base, Al = base + A_BYTES;
        const uint32_t Bh = base + 2 * A_BYTES;
        if (strip_active) {
            if (!aload) {
                hA0 = make_uint4(0u, 0u, 0u, 0u);
                hA1 = lA0 = lA1 = hA0;
            }
            const uint32_t offA = arow * 80 + akh * 2;
            sts128(Ah + offA,      hA0.x, hA0.y, hA0.z, hA0.w);
            sts128(Ah + offA + 16, hA1.x, hA1.y, hA1.z, hA1.w);
            sts128(Al + offA,      lA0.x, lA0.y, lA0.z, lA0.w);
            sts128(Al + offA + 16, lA1.x, lA1.y, lA1.z, lA1.w);
        }
        uint32_t h0, h1, h2, h3;
        const uint32_t offB = brow * 144 + bcol * 2;
        cvt2h(fB[0], h0, h1); cvt2h(fB[1], h2, h3);
        sts128(Bh + offB, h0, h1, h2, h3);
    };

    float acc[2][4][4];
#pragma unroll
    for (int i = 0; i < 2; i++)
#pragma unroll
        for (int j = 0; j < 4; j++)
#pragma unroll
            for (int q = 0; q < 4; q++) acc[i][j][q] = 0.f;

    auto compute = [&](int b) {
        const uint32_t base = sb + 1024 + b * DN_BUF;
        const uint32_t Ah = base, Al = base + A_BYTES;
        const uint32_t Bh = base + 2 * A_BYTES;
#pragma unroll
        for (int kk = 0; kk < 2; kk++) {
            uint32_t ah[2][4], al[2][4];
            const uint32_t acol = (kk * 16 + (lane >> 4) * 8) * 2;
#pragma unroll
            for (int i = 0; i < 2; i++) {
                uint32_t ra = (wm * 32 + i * 16 + (lane & 15)) * 80 + acol;
                ldsm4(ah[i][0], ah[i][1], ah[i][2], ah[i][3], Ah + ra);
                ldsm4(al[i][0], al[i][1], al[i][2], al[i][3], Al + ra);
            }
            const uint32_t brow_ = kk * 16 + ((lane >> 3) & 1) * 8 + (lane & 7);
#pragma unroll
            for (int hf = 0; hf < 2; hf++) {
                const uint32_t rb = brow_ * 144 + (wn * 32 + hf * 16 + (lane >> 4) * 8) * 2;
                uint32_t b0, b1, b2, b3;
                ldsm4t(b0, b1, b2, b3, Bh + rb);
#pragma unroll
                for (int i = 0; i < 2; i++) {
                    float* c0 = acc[i][hf * 2 + 0];
                    float* c1 = acc[i][hf * 2 + 1];
                    mma_h(c0[0], c0[1], c0[2], c0[3], ah[i][0], ah[i][1], ah[i][2], ah[i][3], b0, b1);
                    mma_h(c0[0], c0[1], c0[2], c0[3], al[i][0], al[i][1], al[i][2], al[i][3], b0, b1);
                    mma_h(c1[0], c1[1], c1[2], c1[3], ah[i][0], ah[i][1], ah[i][2], ah[i][3], b2, b3);
                    mma_h(c1[0], c1[1], c1[2], c1[3], al[i][0], al[i][1], al[i][2], al[i][3], b2, b3);
                }
            }
        }
    };

    loadRegs(0);
    stsRegs(0);
    __syncthreads();

    const int C = IDIM / 32;
    for (int c = 0; c < C; c++) {
        if (c + 1 < C) loadRegs((c + 1) * 32);
        if (strip_active) compute(c & 1);
        if (c + 1 < C) { stsRegs((c + 1) & 1); __syncthreads(); }
    }

    if (strip_active) {
#pragma unroll
        for (int i = 0; i < 2; i++)
#pragma unroll
            for (int nt = 0; nt < 4; nt++) {
                const int r   = wm * 32 + i * 16 + (lane >> 2);
                const int cof = n0 + wn * 32 + nt * 8 + (lane & 3) * 2;
#pragma unroll
                for (int half_ = 0; half_ < 2; half_++) {
                    const int rr  = r + half_ * 8;
                    const int ent = sEnt[rr];
                    if (ent >= 0) {
                        float* dst = out + (size_t)(ent >> 3) * HDIM + cof;
                        atomicAdd(dst,     acc[i][nt][half_ * 2 + 0]);
                        atomicAdd(dst + 1, acc[i][nt][half_ * 2 + 1]);
                    }
                }
            }
    }
}

// ---------------- launch ----------------
extern "C" void kernel_launch(void* const* d_in, const int* in_sizes, int n_in,
                              void* d_out, int out_size) {
    const float* x  = (const float*)d_in[0];
    const float* gw = (const float*)d_in[1];
    const float* wg = (const float*)d_in[2];
    const float* wu = (const float*)d_in[3];
    const float* wd = (const float*)d_in[4];
    float* out = (float*)d_out;

    static int smem_set = 0;
    if (!smem_set) {
        cudaFuncSetAttribute(gateup_mma, cudaFuncAttributeMaxDynamicSharedMemorySize, GU_SMEM);
        cudaFuncSetAttribute(down_mma,   cudaFuncAttributeMaxDynamicSharedMemorySize, DN_SMEM);
        smem_set = 1;
    }

    cudaMemsetAsync(out, 0, (size_t)T_TOK * HDIM * sizeof(float));
    zero_counts_kernel<<<1, 64>>>();
    router_kernel<<<T_TOK / 16, 256>>>(x, gw);

    dim3 gu_grid(IDIM / 64, T_TOK / 128, NEXP);
    gateup_mma<<<gu_grid, 256, GU_SMEM>>>(x, wg, wu);

    dim3 dn_grid(HDIM / 64, T_TOK / 128, NEXP);
    down_mma<<<dn_grid, 256, DN_SMEM>>>(wd, out);
}

// round 6
// speedup vs baseline: 2.5328x; 1.0627x over previous
#include <cuda_runtime.h>
#include <cuda_fp16.h>
#include <math.h>
#include <stdint.h>

#define T_TOK 1024
#define HDIM  2048
#define NEXP  64
#define IDIM  768
#define TOPK  8

// ---------------- device scratch ----------------
__device__ int    g_count[NEXP];
__device__ int    g_entry[NEXP * T_TOK];           // token*8 + slot
__device__ float  g_wt   [NEXP * T_TOK];
__device__ __half g_act_h[T_TOK * TOPK * IDIM];    // fp16 hi plane of silu(g)*u*w
__device__ __half g_act_l[T_TOK * TOPK * IDIM];    // fp16 lo plane

// ---------------- helpers ----------------
__device__ __forceinline__ uint32_t smem_u32(const void* p) {
    uint32_t a;
    asm("{ .reg .u64 t; cvta.to.shared.u64 t, %1; cvt.u32.u64 %0, t; }" : "=r"(a) : "l"(p));
    return a;
}
__device__ __forceinline__ void sts128(uint32_t a, uint32_t x, uint32_t y, uint32_t z, uint32_t w) {
    asm volatile("st.shared.v4.b32 [%0], {%1,%2,%3,%4};" :: "r"(a), "r"(x), "r"(y), "r"(z), "r"(w));
}
__device__ __forceinline__ void ldsm4(uint32_t& r0, uint32_t& r1, uint32_t& r2, uint32_t& r3, uint32_t a) {
    asm volatile("ldmatrix.sync.aligned.m8n8.x4.shared.b16 {%0,%1,%2,%3}, [%4];"
                 : "=r"(r0), "=r"(r1), "=r"(r2), "=r"(r3) : "r"(a));
}
__device__ __forceinline__ void ldsm4t(uint32_t& r0, uint32_t& r1, uint32_t& r2, uint32_t& r3, uint32_t a) {
    asm volatile("ldmatrix.sync.aligned.m8n8.x4.trans.shared.b16 {%0,%1,%2,%3}, [%4];"
                 : "=r"(r0), "=r"(r1), "=r"(r2), "=r"(r3) : "r"(a));
}
__device__ __forceinline__ void mma_h(float& c0, float& c1, float& c2, float& c3,
                                      uint32_t a0, uint32_t a1, uint32_t a2, uint32_t a3,
                                      uint32_t b0, uint32_t b1) {
    asm volatile("mma.sync.aligned.m16n8k16.row.col.f32.f16.f16.f32 "
                 "{%0,%1,%2,%3},{%4,%5,%6,%7},{%8,%9},{%0,%1,%2,%3};"
                 : "+f"(c0), "+f"(c1), "+f"(c2), "+f"(c3)
                 : "r"(a0), "r"(a1), "r"(a2), "r"(a3), "r"(b0), "r"(b1));
}
__device__ __forceinline__ uint32_t packh(__half lo, __half hi) {
    return (uint32_t)__half_as_ushort(lo) | ((uint32_t)__half_as_ushort(hi) << 16);
}
// split fp32x4 -> fp16 hi (2 regs) + fp16 lo (2 regs)
__device__ __forceinline__ void cvt4h(float4 f, uint32_t& h0, uint32_t& h1,
                                      uint32_t& l0, uint32_t& l1) {
    __half ax = __float2half_rn(f.x), ay = __float2half_rn(f.y);
    __half az = __float2half_rn(f.z), aw = __float2half_rn(f.w);
    __half bx = __float2half_rn(f.x - __half2float(ax));
    __half by = __float2half_rn(f.y - __half2float(ay));
    __half bz = __float2half_rn(f.z - __half2float(az));
    __half bw = __float2half_rn(f.w - __half2float(aw));
    h0 = packh(ax, ay); h1 = packh(az, aw);
    l0 = packh(bx, by); l1 = packh(bz, bw);
}
// single-plane fp16 convert: fp32x4 -> 2 packed regs
__device__ __forceinline__ void cvt2h(float4 f, uint32_t& h0, uint32_t& h1) {
    __half2 a = __floats2half2_rn(f.x, f.y);
    __half2 b = __floats2half2_rn(f.z, f.w);
    h0 = *(uint32_t*)&a; h1 = *(uint32_t*)&b;
}

// smem geometry (fp16 elems):
//   A tile 128x32, row stride 40 elems (80B, ldsm conflict-free)
//   B64 tile 32x64,  row stride 72 elems (144B, conflict-free)
//   B128 tile 32x128, row stride 136 elems (272B, conflict-free: 272 mod 128 == 16)
#define A_BYTES    10240   // 128*40*2
#define B1_BYTES   4608    // 32*72*2
#define B128_BYTES 8704    // 32*272

// ---------------- kernel 0: reset counters ----------------
__global__ void zero_counts_kernel() {
    if (threadIdx.x < NEXP) g_count[threadIdx.x] = 0;
}

// ---------------- kernel 1: router GEMM + top-8 + bucket scatter ----------------
__global__ __launch_bounds__(256)
void router_kernel(const float* __restrict__ x, const float* __restrict__ gw) {
    __shared__ float As[16][17];
    __shared__ float Bs[16][68];
    __shared__ float Ls[16][68];

    const int t0  = blockIdx.x * 16;
    const int tid = threadIdx.x;
    const int tx  = tid & 15;
    const int ty  = tid >> 4;

    const int am = tid >> 4, ak = tid & 15;
    const int be = tid & 63, bk4 = (tid >> 6) * 4;

    float acc[4] = {0.f, 0.f, 0.f, 0.f};

    for (int k0 = 0; k0 < HDIM; k0 += 16) {
        As[ak][am] = x[(size_t)(t0 + am) * HDIM + k0 + ak];
        float4 bv = *(const float4*)(gw + (size_t)be * HDIM + k0 + bk4);
        Bs[bk4 + 0][be] = bv.x; Bs[bk4 + 1][be] = bv.y;
        Bs[bk4 + 2][be] = bv.z; Bs[bk4 + 3][be] = bv.w;
        __syncthreads();
#pragma unroll
        for (int kk = 0; kk < 16; kk++) {
            float a = As[kk][ty];
#pragma unroll
            for (int j = 0; j < 4; j++) acc[j] += a * Bs[kk][tx * 4 + j];
        }
        __syncthreads();
    }

#pragma unroll
    for (int j = 0; j < 4; j++) Ls[ty][tx * 4 + j] = acc[j];
    __syncthreads();

    if (tid < 16) {
        int   sel[TOPK];
        float sv [TOPK];
        unsigned long long mask = 0ull;
#pragma unroll
        for (int k = 0; k < TOPK; k++) {
            float best = -1e30f;
            int   be_  = 0;
            for (int e = 0; e < NEXP; e++) {
                if ((mask >> e) & 1ull) continue;
                float v = Ls[tid][e];
                if (v > best) { best = v; be_ = e; }
            }
            mask |= (1ull << be_);
            sel[k] = be_;
            sv[k]  = best;
        }
        float mx = sv[0];
        float s  = 0.f;
#pragma unroll
        for (int k = 0; k < TOPK; k++) { sv[k] = expf(sv[k] - mx); s += sv[k]; }
        float inv = 1.f / s;
#pragma unroll
        for (int k = 0; k < TOPK; k++) {
            int e   = sel[k];
            int pos = atomicAdd(&g_count[e], 1);
            g_entry[e * T_TOK + pos] = (t0 + tid) * TOPK + k;
            g_wt   [e * T_TOK + pos] = sv[k] * inv;
        }
    }
}

// ---------------- kernel 2: gate+up HMMA GEMM, fused SwiGLU ----------------
// BM=128 gathered tokens, BN=64 (both gate & up), BK=32.
// A split fp16 hi/lo (2 MMA terms); B single fp16 plane.
#define GU_BUF  (2 * A_BYTES + 2 * B1_BYTES)         // 29696
#define GU_SMEM (1024 + 2 * GU_BUF)                  // 60416

__global__ __launch_bounds__(256, 1)
void gateup_mma(const float* __restrict__ x,
                const float* __restrict__ wg,
                const float* __restrict__ wu) {
    extern __shared__ char smem[];
    const int e   = blockIdx.z;
    const int cnt = g_count[e];
    const int m0  = blockIdx.y * 128;
    if (m0 >= cnt) return;
    const int n0  = blockIdx.x * 64;
    const int tid  = threadIdx.x;
    const int wid  = tid >> 5;
    const int lane = tid & 31;

    const uint32_t sb = smem_u32(smem);
    int*   sEnt = (int*)smem;
    float* sW   = (float*)(smem + 512);

    if (tid < 128) {
        int mi = m0 + tid;
        if (mi < cnt) { sEnt[tid] = g_entry[e * T_TOK + mi]; sW[tid] = g_wt[e * T_TOK + mi]; }
        else          { sEnt[tid] = -1;                      sW[tid] = 0.f; }
    }
    __syncthreads();

    const int wm = wid >> 1, wn = wid & 1;
    const bool strip_active = (m0 + wm * 32) < cnt;

    const int arow = tid >> 1, akh = (tid & 1) * 16;
    const int aent = sEnt[arow];
    const float* ax = x + (size_t)(aent >= 0 ? (aent >> 3) : 0) * HDIM + akh;
    const int brow = tid >> 3, bcol = (tid & 7) * 8;
    const float* pg = wg + (size_t)e * HDIM * IDIM + n0 + bcol;
    const float* pu = wu + (size_t)e * HDIM * IDIM + n0 + bcol;
    const bool aload = strip_active && (aent >= 0);

    float4 fA[4], fG[2], fU[2];
    auto loadRegs = [&](int k0) {
        if (aload) {
            fA[0] = *(const float4*)(ax + k0);
            fA[1] = *(const float4*)(ax + k0 + 4);
            fA[2] = *(const float4*)(ax + k0 + 8);
            fA[3] = *(const float4*)(ax + k0 + 12);
        }
        const float* gp = pg + (size_t)(k0 + brow) * IDIM;
        const float* up = pu + (size_t)(k0 + brow) * IDIM;
        fG[0] = *(const float4*)gp; fG[1] = *(const float4*)(gp + 4);
        fU[0] = *(const float4*)up; fU[1] = *(const float4*)(up + 4);
    };

    auto stsRegs = [&](int b) {
        const uint32_t base = sb + 1024 + b * GU_BUF;
        const uint32_t Ah = base, Al = base + A_BYTES;
        const uint32_t Bg = base + 2 * A_BYTES, Bu = Bg + B1_BYTES;
        uint32_t h0, h1, l0, l1, h2, h3, l2, l3;
        if (strip_active) {
            if (!aload) {
                fA[0] = make_float4(0.f, 0.f, 0.f, 0.f);
                fA[1] = fA[2] = fA[3] = fA[0];
            }
            const uint32_t offA = arow * 80 + akh * 2;
            cvt4h(fA[0], h0, h1, l0, l1); cvt4h(fA[1], h2, h3, l2, l3);
            sts128(Ah + offA, h0, h1, h2, h3); sts128(Al + offA, l0, l1, l2, l3);
            cvt4h(fA[2], h0, h1, l0, l1); cvt4h(fA[3], h2, h3, l2, l3);
            sts128(Ah + offA + 16, h0, h1, h2, h3); sts128(Al + offA + 16, l0, l1, l2, l3);
        }
        const uint32_t offB = brow * 144 + bcol * 2;
        cvt2h(fG[0], h0, h1); cvt2h(fG[1], h2, h3);
        sts128(Bg + offB, h0, h1, h2, h3);
        cvt2h(fU[0], h0, h1); cvt2h(fU[1], h2, h3);
        sts128(Bu + offB, h0, h1, h2, h3);
    };

    float accg[2][4][4], accu[2][4][4];
#pragma unroll
    for (int i = 0; i < 2; i++)
#pragma unroll
        for (int j = 0; j < 4; j++)
#pragma unroll
            for (int q = 0; q < 4; q++) { accg[i][j][q] = 0.f; accu[i][j][q] = 0.f; }

    auto compute = [&](int b) {
        const uint32_t base = sb + 1024 + b * GU_BUF;
        const uint32_t Ah = base, Al = base + A_BYTES;
        const uint32_t Bg = base + 2 * A_BYTES, Bu = Bg + B1_BYTES;
#pragma unroll
        for (int kk = 0; kk < 2; kk++) {
            uint32_t ah[2][4], al[2][4];
            const uint32_t acol = (kk * 16 + (lane >> 4) * 8) * 2;
#pragma unroll
            for (int i = 0; i < 2; i++) {
                uint32_t ra = (wm * 32 + i * 16 + (lane & 15)) * 80 + acol;
                ldsm4(ah[i][0], ah[i][1], ah[i][2], ah[i][3], Ah + ra);
                ldsm4(al[i][0], al[i][1], al[i][2], al[i][3], Al + ra);
            }
            const uint32_t brow_ = kk * 16 + ((lane >> 3) & 1) * 8 + (lane & 7);
#pragma unroll
            for (int hf = 0; hf < 2; hf++) {
                const uint32_t rb = brow_ * 144 + (wn * 32 + hf * 16 + (lane >> 4) * 8) * 2;
                uint32_t g0, g1, g2, g3;
                ldsm4t(g0, g1, g2, g3, Bg + rb);
#pragma unroll
                for (int i = 0; i < 2; i++) {
                    float* c0 = accg[i][hf * 2 + 0];
                    float* c1 = accg[i][hf * 2 + 1];
                    mma_h(c0[0], c0[1], c0[2], c0[3], ah[i][0], ah[i][1], ah[i][2], ah[i][3], g0, g1);
                    mma_h(c0[0], c0[1], c0[2], c0[3], al[i][0], al[i][1], al[i][2], al[i][3], g0, g1);
                    mma_h(c1[0], c1[1], c1[2], c1[3], ah[i][0], ah[i][1], ah[i][2], ah[i][3], g2, g3);
                    mma_h(c1[0], c1[1], c1[2], c1[3], al[i][0], al[i][1], al[i][2], al[i][3], g2, g3);
                }
                uint32_t u0, u1, u2, u3;
                ldsm4t(u0, u1, u2, u3, Bu + rb);
#pragma unroll
                for (int i = 0; i < 2; i++) {
                    float* c0 = accu[i][hf * 2 + 0];
                    float* c1 = accu[i][hf * 2 + 1];
                    mma_h(c0[0], c0[1], c0[2], c0[3], ah[i][0], ah[i][1], ah[i][2], ah[i][3], u0, u1);
                    mma_h(c0[0], c0[1], c0[2], c0[3], al[i][0], al[i][1], al[i][2], al[i][3], u0, u1);
                    mma_h(c1[0], c1[1], c1[2], c1[3], ah[i][0], ah[i][1], ah[i][2], ah[i][3], u2, u3);
                    mma_h(c1[0], c1[1], c1[2], c1[3], al[i][0], al[i][1], al[i][2], al[i][3], u2, u3);
                }
            }
        }
    };

    loadRegs(0);
    stsRegs(0);
    __syncthreads();

    const int C = HDIM / 32;
    for (int c = 0; c < C; c++) {
        if (c + 1 < C) loadRegs((c + 1) * 32);
        if (strip_active) compute(c & 1);
        if (c + 1 < C) { stsRegs((c + 1) & 1); __syncthreads(); }
    }

    if (strip_active) {
#pragma unroll
        for (int i = 0; i < 2; i++)
#pragma unroll
            for (int nt = 0; nt < 4; nt++) {
                const int r    = wm * 32 + i * 16 + (lane >> 2);
                const int cof  = n0 + wn * 32 + nt * 8 + (lane & 3) * 2;
#pragma unroll
                for (int half_ = 0; half_ < 2; half_++) {
                    const int rr  = r + half_ * 8;
                    const int ent = sEnt[rr];
                    if (ent >= 0) {
                        const float w = sW[rr];
                        float g0 = accg[i][nt][half_ * 2 + 0], g1 = accg[i][nt][half_ * 2 + 1];
                        float u0 = accu[i][nt][half_ * 2 + 0], u1 = accu[i][nt][half_ * 2 + 1];
                        float v0 = g0 / (1.f + expf(-g0)) * u0 * w;
                        float v1 = g1 / (1.f + expf(-g1)) * u1 * w;
                        __half h0 = __float2half_rn(v0), h1 = __float2half_rn(v1);
                        __half l0 = __float2half_rn(v0 - __half2float(h0));
                        __half l1 = __float2half_rn(v1 - __half2float(h1));
                        size_t off = (size_t)ent * IDIM + cof;
                        *(__half2*)(g_act_h + off) = __halves2half2(h0, h1);
                        *(__half2*)(g_act_l + off) = __halves2half2(l0, l1);
                    }
                }
            }
    }
}

// ---------------- kernel 3: down HMMA GEMM, BN=128, atomic scatter ----------------
// 8 warps = 4M x 2N; per-warp tile 32M x 64N. A fp16 hi/lo, B single fp16 plane.
#define DN_BUF  (2 * A_BYTES + B128_BYTES)           // 29184
#define DN_SMEM (1024 + 2 * DN_BUF)                  // 59392

__global__ __launch_bounds__(256, 1)
void down_mma(const float* __restrict__ wd, float* __restrict__ out) {
    extern __shared__ char smem[];
    const int e   = blockIdx.z;
    const int cnt = g_count[e];
    const int m0  = blockIdx.y * 128;
    if (m0 >= cnt) return;
    const int n0  = blockIdx.x * 128;
    const int tid  = threadIdx.x;
    const int wid  = tid >> 5;
    const int lane = tid & 31;

    const uint32_t sb = smem_u32(smem);
    int* sEnt = (int*)smem;

    if (tid < 128) {
        int mi = m0 + tid;
        sEnt[tid] = (mi < cnt) ? g_entry[e * T_TOK + mi] : -1;
    }
    __syncthreads();

    const int wm = wid >> 1, wn = wid & 1;
    const bool strip_active = (m0 + wm * 32) < cnt;

    // A loader: 128 rows, 2 threads/row, 16 cols each, hi/lo planes
    const int arow = tid >> 1, akh = (tid & 1) * 16;
    const int aent = sEnt[arow];
    const __half* axh = g_act_h + (size_t)(aent >= 0 ? aent : 0) * IDIM + akh;
    const __half* axl = g_act_l + (size_t)(aent >= 0 ? aent : 0) * IDIM + akh;
    const bool aload = strip_active && (aent >= 0);

    // B loader: 32 rows x 128 cols fp32; 8 threads/row, each thread two 8-col
    // segments at +0 and +64 (keeps LDG coalesced and STS phases 128B-contiguous)
    const int brow = tid >> 3, c8 = (tid & 7) * 8;
    const float* pb = wd + (size_t)e * IDIM * HDIM + n0 + c8;

    uint4 hA0, hA1, lA0, lA1;
    float4 fB[4];
    auto loadRegs = [&](int k0) {
        if (aload) {
            hA0 = *(const uint4*)(axh + k0);
            hA1 = *(const uint4*)(axh + k0 + 8);
            lA0 = *(const uint4*)(axl + k0);
            lA1 = *(const uint4*)(axl + k0 + 8);
        }
        const float* bp = pb + (size_t)(k0 + brow) * HDIM;
        fB[0] = *(const float4*)bp;        fB[1] = *(const float4*)(bp + 4);
        fB[2] = *(const float4*)(bp + 64); fB[3] = *(const float4*)(bp + 68);
    };

    auto stsRegs = [&](int b) {
        const uint32_t base = sb + 1024 + b * DN_BUF;
        const uint32_t Ah = base, Al = base + A_BYTES;
        const uint32_t Bh = base + 2 * A_BYTES;
        if (strip_active) {
            if (!aload) {
                hA0 = make_uint4(0u, 0u, 0u, 0u);
                hA1 = lA0 = lA1 = hA0;
            }
            const uint32_t offA = arow * 80 + akh * 2;
            sts128(Ah + offA,      hA0.x, hA0.y, hA0.z, hA0.w);
            sts128(Ah + offA + 16, hA1.x, hA1.y, hA1.z, hA1.w);
            sts128(Al + offA,      lA0.x, lA0.y, lA0.z, lA0.w);
            sts128(Al + offA + 16, lA1.x, lA1.y, lA1.z, lA1.w);
        }
        uint32_t h0, h1, h2, h3;
        const uint32_t offB = brow * 272 + c8 * 2;
        cvt2h(fB[0], h0, h1); cvt2h(fB[1], h2, h3);
        sts128(Bh + offB, h0, h1, h2, h3);
        cvt2h(fB[2], h0, h1); cvt2h(fB[3], h2, h3);
        sts128(Bh + offB + 128, h0, h1, h2, h3);
    };

    float acc[2][8][4];
#pragma unroll
    for (int i = 0; i < 2; i++)
#pragma unroll
        for (int j = 0; j < 8; j++)
#pragma unroll
            for (int q = 0; q < 4; q++) acc[i][j][q] = 0.f;

    auto compute = [&](int b) {
        const uint32_t base = sb + 1024 + b * DN_BUF;
        const uint32_t Ah = base, Al = base + A_BYTES;
        const uint32_t Bh = base + 2 * A_BYTES;
#pragma unroll
        for (int kk = 0; kk < 2; kk++) {
            uint32_t ah[2][4], al[2][4];
            const uint32_t acol = (kk * 16 + (lane >> 4) * 8) * 2;
#pragma unroll
            for (int i = 0; i < 2; i++) {
                uint32_t ra = (wm * 32 + i * 16 + (lane & 15)) * 80 + acol;
                ldsm4(ah[i][0], ah[i][1], ah[i][2], ah[i][3], Ah + ra);
                ldsm4(al[i][0], al[i][1], al[i][2], al[i][3], Al + ra);
            }
            const uint32_t brow_ = kk * 16 + ((lane >> 3) & 1) * 8 + (lane & 7);
#pragma unroll
            for (int hf = 0; hf < 4; hf++) {
                const uint32_t rb = brow_ * 272 + (wn * 64 + hf * 16 + (lane >> 4) * 8) * 2;
                uint32_t b0, b1, b2, b3;
                ldsm4t(b0, b1, b2, b3, Bh + rb);
#pragma unroll
                for (int i = 0; i < 2; i++) {
                    float* c0 = acc[i][hf * 2 + 0];
                    float* c1 = acc[i][hf * 2 + 1];
                    mma_h(c0[0], c0[1], c0[2], c0[3], ah[i][0], ah[i][1], ah[i][2], ah[i][3], b0, b1);
                    mma_h(c0[0], c0[1], c0[2], c0[3], al[i][0], al[i][1], al[i][2], al[i][3], b0, b1);
                    mma_h(c1[0], c1[1], c1[2], c1[3], ah[i][0], ah[i][1], ah[i][2], ah[i][3], b2, b3);
                    mma_h(c1[0], c1[1], c1[2], c1[3], al[i][0], al[i][1], al[i][2], al[i][3], b2, b3);
                }
            }
        }
    };

    loadRegs(0);
    stsRegs(0);
    __syncthreads();

    const int C = IDIM / 32;
    for (int c = 0; c < C; c++) {
        if (c + 1 < C) loadRegs((c + 1) * 32);
        if (strip_active) compute(c & 1);
        if (c + 1 < C) { stsRegs((c + 1) & 1); __syncthreads(); }
    }

    if (strip_active) {
#pragma unroll
        for (int i = 0; i < 2; i++)
#pragma unroll
            for (int nt = 0; nt < 8; nt++) {
                const int r   = wm * 32 + i * 16 + (lane >> 2);
                const int cof = n0 + wn * 64 + nt * 8 + (lane & 3) * 2;
#pragma unroll
                for (int half_ = 0; half_ < 2; half_++) {
                    const int rr  = r + half_ * 8;
                    const int ent = sEnt[rr];
                    if (ent >= 0) {
                        float* dst = out + (size_t)(ent >> 3) * HDIM + cof;
                        atomicAdd(dst,     acc[i][nt][half_ * 2 + 0]);
                        atomicAdd(dst + 1, acc[i][nt][half_ * 2 + 1]);
                    }
                }
            }
    }
}

// ---------------- launch ----------------
extern "C" void kernel_launch(void* const* d_in, const int* in_sizes, int n_in,
                              void* d_out, int out_size) {
    const float* x  = (const float*)d_in[0];
    const float* gw = (const float*)d_in[1];
    const float* wg = (const float*)d_in[2];
    const float* wu = (const float*)d_in[3];
    const float* wd = (const float*)d_in[4];
    float* out = (float*)d_out;

    static int smem_set = 0;
    if (!smem_set) {
        cudaFuncSetAttribute(gateup_mma, cudaFuncAttributeMaxDynamicSharedMemorySize, GU_SMEM);
        cudaFuncSetAttribute(down_mma,   cudaFuncAttributeMaxDynamicSharedMemorySize, DN_SMEM);
        smem_set = 1;
    }

    cudaMemsetAsync(out, 0, (size_t)T_TOK * HDIM * sizeof(float));
    zero_counts_kernel<<<1, 64>>>();
    router_kernel<<<T_TOK / 16, 256>>>(x, gw);

    dim3 gu_grid(IDIM / 64, T_TOK / 128, NEXP);
    gateup_mma<<<gu_grid, 256, GU_SMEM>>>(x, wg, wu);

    dim3 dn_grid(HDIM / 128, T_TOK / 128, NEXP);
    down_mma<<<dn_grid, 256, DN_SMEM>>>(wd, out);
}

// round 7
// speedup vs baseline: 3.9119x; 1.5445x over previous
#include <cuda_runtime.h>
#include <cuda_fp16.h>
#include <math.h>
#include <stdint.h>

#define T_TOK 1024
#define HDIM  2048
#define NEXP  64
#define IDIM  768
#define TOPK  8

// ---------------- device scratch ----------------
__device__ int    g_count[NEXP];
__device__ int    g_entry[NEXP * T_TOK];           // token*8 + slot
__device__ float  g_wt   [NEXP * T_TOK];
__device__ __half g_act  [T_TOK * TOPK * IDIM];    // fp16 silu(g)*u*w, gathered

// ---------------- helpers ----------------
__device__ __forceinline__ uint32_t smem_u32(const void* p) {
    uint32_t a;
    asm("{ .reg .u64 t; cvta.to.shared.u64 t, %1; cvt.u32.u64 %0, t; }" : "=r"(a) : "l"(p));
    return a;
}
__device__ __forceinline__ void sts128(uint32_t a, uint32_t x, uint32_t y, uint32_t z, uint32_t w) {
    asm volatile("st.shared.v4.b32 [%0], {%1,%2,%3,%4};" :: "r"(a), "r"(x), "r"(y), "r"(z), "r"(w));
}
__device__ __forceinline__ void ldsm4(uint32_t& r0, uint32_t& r1, uint32_t& r2, uint32_t& r3, uint32_t a) {
    asm volatile("ldmatrix.sync.aligned.m8n8.x4.shared.b16 {%0,%1,%2,%3}, [%4];"
                 : "=r"(r0), "=r"(r1), "=r"(r2), "=r"(r3) : "r"(a));
}
__device__ __forceinline__ void ldsm4t(uint32_t& r0, uint32_t& r1, uint32_t& r2, uint32_t& r3, uint32_t a) {
    asm volatile("ldmatrix.sync.aligned.m8n8.x4.trans.shared.b16 {%0,%1,%2,%3}, [%4];"
                 : "=r"(r0), "=r"(r1), "=r"(r2), "=r"(r3) : "r"(a));
}
__device__ __forceinline__ void mma_h(float& c0, float& c1, float& c2, float& c3,
                                      uint32_t a0, uint32_t a1, uint32_t a2, uint32_t a3,
                                      uint32_t b0, uint32_t b1) {
    asm volatile("mma.sync.aligned.m16n8k16.row.col.f32.f16.f16.f32 "
                 "{%0,%1,%2,%3},{%4,%5,%6,%7},{%8,%9},{%0,%1,%2,%3};"
                 : "+f"(c0), "+f"(c1), "+f"(c2), "+f"(c3)
                 : "r"(a0), "r"(a1), "r"(a2), "r"(a3), "r"(b0), "r"(b1));
}
// single-plane fp16 convert: fp32x4 -> 2 packed regs
__device__ __forceinline__ void cvt2h(float4 f, uint32_t& h0, uint32_t& h1) {
    __half2 a = __floats2half2_rn(f.x, f.y);
    __half2 b = __floats2half2_rn(f.z, f.w);
    h0 = *(uint32_t*)&a; h1 = *(uint32_t*)&b;
}

// smem geometry (fp16 elems):
//   A tile 128x32, row stride 40 elems (80B, ldsm conflict-free)
//   B64 tile 32x64,  row stride 72 elems (144B, conflict-free)
//   B128 tile 32x128, row stride 136 elems (272B, conflict-free: 272 mod 128 == 16)
#define A_BYTES    10240   // 128*40*2
#define B1_BYTES   4608    // 32*72*2
#define B128_BYTES 8704    // 32*272

// ---------------- kernel 0: reset counters ----------------
__global__ void zero_counts_kernel() {
    if (threadIdx.x < NEXP) g_count[threadIdx.x] = 0;
}

// ---------------- kernel 1: router GEMM + top-8 + bucket scatter ----------------
__global__ __launch_bounds__(256)
void router_kernel(const float* __restrict__ x, const float* __restrict__ gw) {
    __shared__ float As[16][17];
    __shared__ float Bs[16][68];
    __shared__ float Ls[16][68];

    const int t0  = blockIdx.x * 16;
    const int tid = threadIdx.x;
    const int tx  = tid & 15;
    const int ty  = tid >> 4;

    const int am = tid >> 4, ak = tid & 15;
    const int be = tid & 63, bk4 = (tid >> 6) * 4;

    float acc[4] = {0.f, 0.f, 0.f, 0.f};

    for (int k0 = 0; k0 < HDIM; k0 += 16) {
        As[ak][am] = x[(size_t)(t0 + am) * HDIM + k0 + ak];
        float4 bv = *(const float4*)(gw + (size_t)be * HDIM + k0 + bk4);
        Bs[bk4 + 0][be] = bv.x; Bs[bk4 + 1][be] = bv.y;
        Bs[bk4 + 2][be] = bv.z; Bs[bk4 + 3][be] = bv.w;
        __syncthreads();
#pragma unroll
        for (int kk = 0; kk < 16; kk++) {
            float a = As[kk][ty];
#pragma unroll
            for (int j = 0; j < 4; j++) acc[j] += a * Bs[kk][tx * 4 + j];
        }
        __syncthreads();
    }

#pragma unroll
    for (int j = 0; j < 4; j++) Ls[ty][tx * 4 + j] = acc[j];
    __syncthreads();

    if (tid < 16) {
        int   sel[TOPK];
        float sv [TOPK];
        unsigned long long mask = 0ull;
#pragma unroll
        for (int k = 0; k < TOPK; k++) {
            float best = -1e30f;
            int   be_  = 0;
            for (int e = 0; e < NEXP; e++) {
                if ((mask >> e) & 1ull) continue;
                float v = Ls[tid][e];
                if (v > best) { best = v; be_ = e; }
            }
            mask |= (1ull << be_);
            sel[k] = be_;
            sv[k]  = best;
        }
        float mx = sv[0];
        float s  = 0.f;
#pragma unroll
        for (int k = 0; k < TOPK; k++) { sv[k] = expf(sv[k] - mx); s += sv[k]; }
        float inv = 1.f / s;
#pragma unroll
        for (int k = 0; k < TOPK; k++) {
            int e   = sel[k];
            int pos = atomicAdd(&g_count[e], 1);
            g_entry[e * T_TOK + pos] = (t0 + tid) * TOPK + k;
            g_wt   [e * T_TOK + pos] = sv[k] * inv;
        }
    }
}

// ---------------- kernel 2: gate+up HMMA GEMM, fused SwiGLU ----------------
// BM=128 gathered tokens, BN=64 (both gate & up), BK=32.
// A single fp16 plane, B single fp16 plane (1 MMA term each).
#define GU_BUF  (A_BYTES + 2 * B1_BYTES)             // 19456
#define GU_SMEM (1024 + 2 * GU_BUF)                  // 39936

__global__ __launch_bounds__(256, 2)
void gateup_mma(const float* __restrict__ x,
                const float* __restrict__ wg,
                const float* __restrict__ wu) {
    extern __shared__ char smem[];
    const int e   = blockIdx.z;
    const int cnt = g_count[e];
    const int m0  = blockIdx.y * 128;
    if (m0 >= cnt) return;
    const int n0  = blockIdx.x * 64;
    const int tid  = threadIdx.x;
    const int wid  = tid >> 5;
    const int lane = tid & 31;

    const uint32_t sb = smem_u32(smem);
    int*   sEnt = (int*)smem;
    float* sW   = (float*)(smem + 512);

    if (tid < 128) {
        int mi = m0 + tid;
        if (mi < cnt) { sEnt[tid] = g_entry[e * T_TOK + mi]; sW[tid] = g_wt[e * T_TOK + mi]; }
        else          { sEnt[tid] = -1;                      sW[tid] = 0.f; }
    }
    __syncthreads();

    const int wm = wid >> 1, wn = wid & 1;
    const bool strip_active = (m0 + wm * 32) < cnt;   // fill strip == compute strip (tid>>6)

    const int arow = tid >> 1, akh = (tid & 1) * 16;
    const int aent = sEnt[arow];
    const float* ax = x + (size_t)(aent >= 0 ? (aent >> 3) : 0) * HDIM + akh;
    const int brow = tid >> 3, bcol = (tid & 7) * 8;
    const float* pg = wg + (size_t)e * HDIM * IDIM + n0 + bcol;
    const float* pu = wu + (size_t)e * HDIM * IDIM + n0 + bcol;
    const bool aload = strip_active && (aent >= 0);

    float4 fA[4], fG[2], fU[2];
    auto loadRegs = [&](int k0) {
        if (aload) {
            fA[0] = *(const float4*)(ax + k0);
            fA[1] = *(const float4*)(ax + k0 + 4);
            fA[2] = *(const float4*)(ax + k0 + 8);
            fA[3] = *(const float4*)(ax + k0 + 12);
        }
        const float* gp = pg + (size_t)(k0 + brow) * IDIM;
        const float* up = pu + (size_t)(k0 + brow) * IDIM;
        fG[0] = *(const float4*)gp; fG[1] = *(const float4*)(gp + 4);
        fU[0] = *(const float4*)up; fU[1] = *(const float4*)(up + 4);
    };

    auto stsRegs = [&](int b) {
        const uint32_t base = sb + 1024 + b * GU_BUF;
        const uint32_t Ah = base;
        const uint32_t Bg = base + A_BYTES, Bu = Bg + B1_BYTES;
        uint32_t h0, h1, h2, h3;
        if (strip_active) {
            if (!aload) {
                fA[0] = make_float4(0.f, 0.f, 0.f, 0.f);
                fA[1] = fA[2] = fA[3] = fA[0];
            }
            const uint32_t offA = arow * 80 + akh * 2;
            cvt2h(fA[0], h0, h1); cvt2h(fA[1], h2, h3);
            sts128(Ah + offA, h0, h1, h2, h3);
            cvt2h(fA[2], h0, h1); cvt2h(fA[3], h2, h3);
            sts128(Ah + offA + 16, h0, h1, h2, h3);
        }
        const uint32_t offB = brow * 144 + bcol * 2;
        cvt2h(fG[0], h0, h1); cvt2h(fG[1], h2, h3);
        sts128(Bg + offB, h0, h1, h2, h3);
        cvt2h(fU[0], h0, h1); cvt2h(fU[1], h2, h3);
        sts128(Bu + offB, h0, h1, h2, h3);
    };

    float accg[2][4][4], accu[2][4][4];
#pragma unroll
    for (int i = 0; i < 2; i++)
#pragma unroll
        for (int j = 0; j < 4; j++)
#pragma unroll
            for (int q = 0; q < 4; q++) { accg[i][j][q] = 0.f; accu[i][j][q] = 0.f; }

    auto compute = [&](int b) {
        const uint32_t base = sb + 1024 + b * GU_BUF;
        const uint32_t Ah = base;
        const uint32_t Bg = base + A_BYTES, Bu = Bg + B1_BYTES;
#pragma unroll
        for (int kk = 0; kk < 2; kk++) {
            uint32_t ah[2][4];
            const uint32_t acol = (kk * 16 + (lane >> 4) * 8) * 2;
#pragma unroll
            for (int i = 0; i < 2; i++) {
                uint32_t ra = (wm * 32 + i * 16 + (lane & 15)) * 80 + acol;
                ldsm4(ah[i][0], ah[i][1], ah[i][2], ah[i][3], Ah + ra);
            }
            const uint32_t brow_ = kk * 16 + ((lane >> 3) & 1) * 8 + (lane & 7);
#pragma unroll
            for (int hf = 0; hf < 2; hf++) {
                const uint32_t rb = brow_ * 144 + (wn * 32 + hf * 16 + (lane >> 4) * 8) * 2;
                uint32_t g0, g1, g2, g3;
                ldsm4t(g0, g1, g2, g3, Bg + rb);
#pragma unroll
                for (int i = 0; i < 2; i++) {
                    float* c0 = accg[i][hf * 2 + 0];
                    float* c1 = accg[i][hf * 2 + 1];
                    mma_h(c0[0], c0[1], c0[2], c0[3], ah[i][0], ah[i][1], ah[i][2], ah[i][3], g0, g1);
                    mma_h(c1[0], c1[1], c1[2], c1[3], ah[i][0], ah[i][1], ah[i][2], ah[i][3], g2, g3);
                }
                uint32_t u0, u1, u2, u3;
                ldsm4t(u0, u1, u2, u3, Bu + rb);
#pragma unroll
                for (int i = 0; i < 2; i++) {
                    float* c0 = accu[i][hf * 2 + 0];
                    float* c1 = accu[i][hf * 2 + 1];
                    mma_h(c0[0], c0[1], c0[2], c0[3], ah[i][0], ah[i][1], ah[i][2], ah[i][3], u0, u1);
                    mma_h(c1[0], c1[1], c1[2], c1[3], ah[i][0], ah[i][1], ah[i][2], ah[i][3], u2, u3);
                }
            }
        }
    };

    loadRegs(0);
    stsRegs(0);
    __syncthreads();

    const int C = HDIM / 32;
    for (int c = 0; c < C; c++) {
        if (c + 1 < C) loadRegs((c + 1) * 32);
        if (strip_active) compute(c & 1);
        if (c + 1 < C) { stsRegs((c + 1) & 1); __syncthreads(); }
    }

    // epilogue: silu(g)*u*w -> fp16 plane
    if (strip_active) {
#pragma unroll
        for (int i = 0; i < 2; i++)
#pragma unroll
            for (int nt = 0; nt < 4; nt++) {
                const int r    = wm * 32 + i * 16 + (lane >> 2);
                const int cof  = n0 + wn * 32 + nt * 8 + (lane & 3) * 2;
#pragma unroll
                for (int half_ = 0; half_ < 2; half_++) {
                    const int rr  = r + half_ * 8;
                    const int ent = sEnt[rr];
                    if (ent >= 0) {
                        const float w = sW[rr];
                        float g0 = accg[i][nt][half_ * 2 + 0], g1 = accg[i][nt][half_ * 2 + 1];
                        float u0 = accu[i][nt][half_ * 2 + 0], u1 = accu[i][nt][half_ * 2 + 1];
                        float v0 = g0 / (1.f + expf(-g0)) * u0 * w;
                        float v1 = g1 / (1.f + expf(-g1)) * u1 * w;
                        *(__half2*)(g_act + (size_t)ent * IDIM + cof) =
                            __floats2half2_rn(v0, v1);
                    }
                }
            }
    }
}

// ---------------- kernel 3: down HMMA GEMM, BN=128, atomic scatter ----------------
// 8 warps = 4M x 2N; per-warp tile 32M x 64N. A single fp16 plane, B fp16.
#define DN_BUF  (A_BYTES + B128_BYTES)               // 18944
#define DN_SMEM (1024 + 2 * DN_BUF)                  // 38912

__global__ __launch_bounds__(256, 2)
void down_mma(const float* __restrict__ wd, float* __restrict__ out) {
    extern __shared__ char smem[];
    const int e   = blockIdx.z;
    const int cnt = g_count[e];
    const int m0  = blockIdx.y * 128;
    if (m0 >= cnt) return;
    const int n0  = blockIdx.x * 128;
    const int tid  = threadIdx.x;
    const int wid  = tid >> 5;
    const int lane = tid & 31;

    const uint32_t sb = smem_u32(smem);
    int* sEnt = (int*)smem;

    if (tid < 128) {
        int mi = m0 + tid;
        sEnt[tid] = (mi < cnt) ? g_entry[e * T_TOK + mi] : -1;
    }
    __syncthreads();

    const int wm = wid >> 1, wn = wid & 1;
    const bool strip_active = (m0 + wm * 32) < cnt;

    const int arow = tid >> 1, akh = (tid & 1) * 16;
    const int aent = sEnt[arow];
    const __half* axh = g_act + (size_t)(aent >= 0 ? aent : 0) * IDIM + akh;
    const bool aload = strip_active && (aent >= 0);

    const int brow = tid >> 3, c8 = (tid & 7) * 8;
    const float* pb = wd + (size_t)e * IDIM * HDIM + n0 + c8;

    uint4 hA0, hA1;
    float4 fB[4];
    auto loadRegs = [&](int k0) {
        if (aload) {
            hA0 = *(const uint4*)(axh + k0);
            hA1 = *(const uint4*)(axh + k0 + 8);
        }
        const float* bp = pb + (size_t)(k0 + brow) * HDIM;
        fB[0] = *(const float4*)bp;        fB[1] = *(const float4*)(bp + 4);
        fB[2] = *(const float4*)(bp + 64); fB[3] = *(const float4*)(bp + 68);
    };

    auto stsRegs = [&](int b) {
        const uint32_t base = sb + 1024 + b * DN_BUF;
        const uint32_t Ah = base;
        const uint32_t Bh = base + A_BYTES;
        if (strip_active) {
            if (!aload) {
                hA0 = make_uint4(0u, 0u, 0u, 0u);
                hA1 = hA0;
            }
            const uint32_t offA = arow * 80 + akh * 2;
            sts128(Ah + offA,      hA0.x, hA0.y, hA0.z, hA0.w);
            sts128(Ah + offA + 16, hA1.x, hA1.y, hA1.z, hA1.w);
        }
        uint32_t h0, h1, h2, h3;
        const uint32_t offB = brow * 272 + c8 * 2;
        cvt2h(fB[0], h0, h1); cvt2h(fB[1], h2, h3);
        sts128(Bh + offB, h0, h1, h2, h3);
        cvt2h(fB[2], h0, h1); cvt2h(fB[3], h2, h3);
        sts128(Bh + offB + 128, h0, h1, h2, h3);
    };

    float acc[2][8][4];
#pragma unroll
    for (int i = 0; i < 2; i++)
#pragma unroll
        for (int j = 0; j < 8; j++)
#pragma unroll
            for (int q = 0; q < 4; q++) acc[i][j][q] = 0.f;

    auto compute = [&](int b) {
        const uint32_t base = sb + 1024 + b * DN_BUF;
        const uint32_t Ah = base;
        const uint32_t Bh = base + A_BYTES;
#pragma unroll
        for (int kk = 0; kk < 2; kk++) {
            uint32_t ah[2][4];
            const uint32_t acol = (kk * 16 + (lane >> 4) * 8) * 2;
#pragma unroll
            for (int i = 0; i < 2; i++) {
                uint32_t ra = (wm * 32 + i * 16 + (lane & 15)) * 80 + acol;
                ldsm4(ah[i][0], ah[i][1], ah[i][2], ah[i][3], Ah + ra);
            }
            const uint32_t brow_ = kk * 16 + ((lane >> 3) & 1) * 8 + (lane & 7);
#pragma unroll
            for (int hf = 0; hf < 4; hf++) {
                const uint32_t rb = brow_ * 272 + (wn * 64 + hf * 16 + (lane >> 4) * 8) * 2;
                uint32_t b0, b1, b2, b3;
                ldsm4t(b0, b1, b2, b3, Bh + rb);
#pragma unroll
                for (int i = 0; i < 2; i++) {
                    float* c0 = acc[i][hf * 2 + 0];
                    float* c1 = acc[i][hf * 2 + 1];
                    mma_h(c0[0], c0[1], c0[2], c0[3], ah[i][0], ah[i][1], ah[i][2], ah[i][3], b0, b1);
                    mma_h(c1[0], c1[1], c1[2], c1[3], ah[i][0], ah[i][1], ah[i][2], ah[i][3], b2, b3);
                }
            }
        }
    };

    loadRegs(0);
    stsRegs(0);
    __syncthreads();

    const int C = IDIM / 32;
    for (int c = 0; c < C; c++) {
        if (c + 1 < C) loadRegs((c + 1) * 32);
        if (strip_active) compute(c & 1);
        if (c + 1 < C) { stsRegs((c + 1) & 1); __syncthreads(); }
    }

    if (strip_active) {
#pragma unroll
        for (int i = 0; i < 2; i++)
#pragma unroll
            for (int nt = 0; nt < 8; nt++) {
                const int r   = wm * 32 + i * 16 + (lane >> 2);
                const int cof = n0 + wn * 64 + nt * 8 + (lane & 3) * 2;
#pragma unroll
                for (int half_ = 0; half_ < 2; half_++) {
                    const int rr  = r + half_ * 8;
                    const int ent = sEnt[rr];
                    if (ent >= 0) {
                        float* dst = out + (size_t)(ent >> 3) * HDIM + cof;
                        atomicAdd(dst,     acc[i][nt][half_ * 2 + 0]);
                        atomicAdd(dst + 1, acc[i][nt][half_ * 2 + 1]);
                    }
                }
            }
    }
}

// ---------------- launch ----------------
extern "C" void kernel_launch(void* const* d_in, const int* in_sizes, int n_in,
                              void* d_out, int out_size) {
    const float* x  = (const float*)d_in[0];
    const float* gw = (const float*)d_in[1];
    const float* wg = (const float*)d_in[2];
    const float* wu = (const float*)d_in[3];
    const float* wd = (const float*)d_in[4];
    float* out = (float*)d_out;

    static int smem_set = 0;
    if (!smem_set) {
        cudaFuncSetAttribute(gateup_mma, cudaFuncAttributeMaxDynamicSharedMemorySize, GU_SMEM);
        cudaFuncSetAttribute(down_mma,   cudaFuncAttributeMaxDynamicSharedMemorySize, DN_SMEM);
        smem_set = 1;
    }

    cudaMemsetAsync(out, 0, (size_t)T_TOK * HDIM * sizeof(float));
    zero_counts_kernel<<<1, 64>>>();
    router_kernel<<<T_TOK / 16, 256>>>(x, gw);

    dim3 gu_grid(IDIM / 64, T_TOK / 128, NEXP);
    gateup_mma<<<gu_grid, 256, GU_SMEM>>>(x, wg, wu);

    dim3 dn_grid(HDIM / 128, T_TOK / 128, NEXP);
    down_mma<<<dn_grid, 256, DN_SMEM>>>(wd, out);
}